// round 8
// baseline (speedup 1.0000x reference)
#include <cuda_runtime.h>
#include <cuda_bf16.h>
#include <math.h>
#include <stdint.h>

#define SEQ 2048
#define DM  1024
#define NH  16
#define DK  64
#define DFF 4096
#define NL  4

typedef __nv_bfloat16 bf16;

// ---------------- device scratch (no cudaMalloc allowed) ----------------
__device__ bf16 g_wqT_h[NL * DM * DM], g_wqT_l[NL * DM * DM];
__device__ bf16 g_wkT_h[NL * DM * DM], g_wkT_l[NL * DM * DM];
__device__ bf16 g_wvT_h[NL * DM * DM], g_wvT_l[NL * DM * DM];
__device__ bf16 g_woT_h[NL * DM * DM], g_woT_l[NL * DM * DM];
__device__ bf16 g_w1T_h[NL * DM * DFF], g_w1T_l[NL * DM * DFF];
__device__ bf16 g_w2T_h[NL * DM * DFF], g_w2T_l[NL * DM * DFF];
__device__ bf16 g_xh[SEQ * DM], g_xl[SEQ * DM];
__device__ bf16 g_qh[SEQ * DM], g_ql[SEQ * DM];
__device__ bf16 g_kh[SEQ * DM], g_kl[SEQ * DM];
__device__ bf16 g_vh[SEQ * DM], g_vl[SEQ * DM];
__device__ bf16 g_vth[DM * SEQ], g_vtl[DM * SEQ];   // V^T
__device__ bf16 g_ch[SEQ * DM], g_cl[SEQ * DM];
__device__ bf16 g_hh[SEQ * DFF], g_hl[SEQ * DFF];
__device__ float g_tmp[SEQ * DM];

// ---------------- small helpers ----------------
__device__ __forceinline__ float gelu_f(float v) {
    return 0.5f * v * (1.0f + tanhf(0.7978845608028654f * (v + 0.044715f * v * v * v)));
}
__device__ __forceinline__ void split_bf(float v, bf16& h, bf16& l) {
    h = __float2bfloat16(v);
    l = __float2bfloat16(v - __bfloat162float(h));
}
__device__ __forceinline__ void cpa16(uint32_t dst, const void* src) {
    asm volatile("cp.async.cg.shared.global [%0], [%1], 16;" :: "r"(dst), "l"(src));
}
#define CP_COMMIT() asm volatile("cp.async.commit_group;" ::: "memory")
#define CP_WAIT0()  asm volatile("cp.async.wait_group 0;" ::: "memory")
#define CP_WAIT1()  asm volatile("cp.async.wait_group 1;" ::: "memory")
#define LDSM4(r, a) asm volatile( \
    "ldmatrix.sync.aligned.m8n8.x4.shared.b16 {%0,%1,%2,%3}, [%4];" \
    : "=r"((r)[0]), "=r"((r)[1]), "=r"((r)[2]), "=r"((r)[3]) : "r"(a))

__device__ __forceinline__ void mma16816(float* c, const uint32_t* a, const uint32_t* b) {
    asm volatile(
        "mma.sync.aligned.m16n8k16.row.col.f32.bf16.bf16.f32 "
        "{%0,%1,%2,%3}, {%4,%5,%6,%7}, {%8,%9}, {%0,%1,%2,%3};"
        : "+f"(c[0]), "+f"(c[1]), "+f"(c[2]), "+f"(c[3])
        : "r"(a[0]), "r"(a[1]), "r"(a[2]), "r"(a[3]), "r"(b[0]), "r"(b[1]));
}
__device__ __forceinline__ uint32_t sm_addr(const void* p) {
    return (uint32_t)__cvta_generic_to_shared(p);
}
__device__ __forceinline__ void pack_split2(float x, float y, uint32_t& h, uint32_t& l) {
    __nv_bfloat162 hh, ll;
    hh.x = __float2bfloat16(x); ll.x = __float2bfloat16(x - __bfloat162float(hh.x));
    hh.y = __float2bfloat16(y); ll.y = __float2bfloat16(y - __bfloat162float(hh.y));
    h = *(uint32_t*)&hh; l = *(uint32_t*)&ll;
}

// ---------------- mma.sync GEMM v2: 128x64 tile, 3-stage, 2 CTA/SM ----------------
// D[128, 64] tile of (A @ B^T) [+bias][gelu]; A,B split hi/lo, K-contiguous.
// EPI: 1 f32+bias, 2 split+bias, 4 gelu(v+bias) split
template <int EPI>
__global__ __launch_bounds__(256, 2) void mmsync(
    const bf16* __restrict__ Ah, const bf16* __restrict__ Al,
    const bf16* __restrict__ Bh, const bf16* __restrict__ Bl,
    const float* __restrict__ bias,
    float* __restrict__ Cf, bf16* __restrict__ Ch, bf16* __restrict__ Cl,
    int K, int lda, int ldb, int ldc)
{
    constexpr int SP = 40;                 // padded row stride (halfs) for BK=32
    constexpr int AST = 128 * SP;          // A stage size (halfs)
    constexpr int BST = 64 * SP;           // B stage size

    extern __shared__ bf16 sm[];
    bf16* sAH = sm;                        // 3 * AST
    bf16* sAL = sAH + 3 * AST;
    bf16* sBH = sAL + 3 * AST;             // 3 * BST
    bf16* sBL = sBH + 3 * BST;

    const int tid = threadIdx.x;
    const int wid = tid >> 5;
    const int lane = tid & 31;
    const int gid = lane >> 2, tig = lane & 3;
    const int bm = blockIdx.y * 128;
    const int bn = blockIdx.x * 64;

    const int wm0 = (wid >> 1) * 32;       // 4 warps along M
    const int wn0 = (wid & 1) * 32;        // 2 warps along N

    float acc[2][4][4];
#pragma unroll
    for (int i = 0; i < 2; i++)
#pragma unroll
        for (int j = 0; j < 4; j++)
#pragma unroll
            for (int q = 0; q < 4; q++) acc[i][j][q] = 0.f;

    const int nk = K >> 5;

    auto loadStage = [&](int st, int k0) {
#pragma unroll
        for (int i = 0; i < 2; i++) {
            int ch = tid + i * 256;        // 512 chunks: row = ch/4, c = ch%4
            int row = ch >> 2, c = ch & 3;
            size_t g = (size_t)(bm + row) * lda + k0 + c * 8;
            int so = st * AST + row * SP + c * 8;
            cpa16(sm_addr(&sAH[so]), Ah + g);
            cpa16(sm_addr(&sAL[so]), Al + g);
        }
        {
            int row = tid >> 2, c = tid & 3;
            size_t g = (size_t)(bn + row) * ldb + k0 + c * 8;
            int so = st * BST + row * SP + c * 8;
            cpa16(sm_addr(&sBH[so]), Bh + g);
            cpa16(sm_addr(&sBL[so]), Bl + g);
        }
    };

    loadStage(0, 0); CP_COMMIT();
    loadStage(1, 32); CP_COMMIT();

    const int ar = lane & 15;
    const int acb = (lane >> 4) << 3;
    const int br = (lane < 16) ? (lane & 7) : 8 + (lane & 7);
    const int bcsel = ((lane >> 3) & 1) << 3;

    for (int kt = 0; kt < nk; kt++) {
        if (kt < nk - 1) CP_WAIT1(); else CP_WAIT0();
        __syncthreads();
        if (kt + 2 < nk) {
            int nx = kt + 2;
            loadStage(nx - (nx / 3) * 3, nx << 5);
            CP_COMMIT();
        }

        const int st = kt - (kt / 3) * 3;
        const bf16* aH = sAH + st * AST;
        const bf16* aL = sAL + st * AST;
        const bf16* bH = sBH + st * BST;
        const bf16* bL = sBL + st * BST;

#pragma unroll
        for (int kk = 0; kk < 2; kk++) {
            const int koff = kk * 16;
            uint32_t ah[2][4], al[2][4];
#pragma unroll
            for (int mf = 0; mf < 2; mf++) {
                int r = wm0 + mf * 16 + ar;
                LDSM4(ah[mf], sm_addr(&aH[r * SP + koff + acb]));
                LDSM4(al[mf], sm_addr(&aL[r * SP + koff + acb]));
            }
            uint32_t bh[4][2], bl[4][2];
            const int bc = koff + bcsel;
#pragma unroll
            for (int nn = 0; nn < 4; nn += 2) {
                int r = wn0 + nn * 8 + br;
                uint32_t t[4];
                LDSM4(t, sm_addr(&bH[r * SP + bc]));
                bh[nn][0] = t[0]; bh[nn][1] = t[1];
                bh[nn + 1][0] = t[2]; bh[nn + 1][1] = t[3];
                LDSM4(t, sm_addr(&bL[r * SP + bc]));
                bl[nn][0] = t[0]; bl[nn][1] = t[1];
                bl[nn + 1][0] = t[2]; bl[nn + 1][1] = t[3];
            }
#pragma unroll
            for (int mf = 0; mf < 2; mf++)
#pragma unroll
                for (int nf = 0; nf < 4; nf++) {
                    mma16816(acc[mf][nf], ah[mf], bh[nf]);
                    mma16816(acc[mf][nf], ah[mf], bl[nf]);
                    mma16816(acc[mf][nf], al[mf], bh[nf]);
                }
        }
    }

    // ---------------- epilogue ----------------
#pragma unroll
    for (int mf = 0; mf < 2; mf++) {
        const int mA = bm + wm0 + mf * 16 + gid;
        const int mB = mA + 8;
#pragma unroll
        for (int nf = 0; nf < 4; nf++) {
            const int n = bn + wn0 + nf * 8 + 2 * tig;
            float c0 = acc[mf][nf][0], c1 = acc[mf][nf][1];
            float c2 = acc[mf][nf][2], c3 = acc[mf][nf][3];
            float b0 = bias[n], b1 = bias[n + 1];
            if (EPI == 1) {
                float2 u = make_float2(c0 + b0, c1 + b1);
                float2 w = make_float2(c2 + b0, c3 + b1);
                *(float2*)(Cf + (size_t)mA * ldc + n) = u;
                *(float2*)(Cf + (size_t)mB * ldc + n) = w;
            } else {
                float v0 = c0 + b0, v1 = c1 + b1, v2 = c2 + b0, v3 = c3 + b1;
                if (EPI == 4) {
                    v0 = gelu_f(v0); v1 = gelu_f(v1);
                    v2 = gelu_f(v2); v3 = gelu_f(v3);
                }
                uint32_t h01, l01, h23, l23;
                pack_split2(v0, v1, h01, l01);
                pack_split2(v2, v3, h23, l23);
                *(uint32_t*)(Ch + (size_t)mA * ldc + n) = h01;
                *(uint32_t*)(Cl + (size_t)mA * ldc + n) = l01;
                *(uint32_t*)(Ch + (size_t)mB * ldc + n) = h23;
                *(uint32_t*)(Cl + (size_t)mB * ldc + n) = l23;
            }
        }
    }
}

// ---------------- flash attention: S=QK^T/8, online softmax, O=PV ----------------
// grid (NH, SEQ/128), 256 threads (8 warps x 16 q-rows), 3-stage KV pipeline
__global__ __launch_bounds__(256) void flash_attn(
    const bf16* __restrict__ qh_g, const bf16* __restrict__ ql_g,
    const bf16* __restrict__ kh_g, const bf16* __restrict__ kl_g,
    const bf16* __restrict__ vth_g, const bf16* __restrict__ vtl_g,
    bf16* __restrict__ ch_g, bf16* __restrict__ cl_g)
{
    constexpr int KSP = 72, VSP = 136;
    constexpr int KST = 128 * KSP;         // 9216 halfs
    constexpr int VST = 64 * VSP;          // 8704 halfs
    const int h = blockIdx.x;
    const int q0 = blockIdx.y * 128;
    const int tid = threadIdx.x, wid = tid >> 5, lane = tid & 31;
    const int gid = lane >> 2, tig = lane & 3;

    extern __shared__ bf16 sm[];
    bf16* sKH = sm;                        // 3 * KST
    bf16* sKL = sKH + 3 * KST;
    bf16* sVH = sKL + 3 * KST;             // 3 * VST
    bf16* sVL = sVH + 3 * VST;

    // ---- prologue: Q tile into stage-0 K buffers, extract frags ----
#pragma unroll
    for (int i = 0; i < 4; i++) {
        int ch = tid + i * 256;
        int row = ch >> 3, c = ch & 7;
        size_t g = (size_t)(q0 + row) * DM + h * 64 + c * 8;
        cpa16(sm_addr(&sKH[row * KSP + c * 8]), qh_g + g);
        cpa16(sm_addr(&sKL[row * KSP + c * 8]), ql_g + g);
    }
    CP_COMMIT(); CP_WAIT0();
    __syncthreads();

    uint32_t qfh[4][4], qfl[4][4];
    {
        const int ar = lane & 15, acb = (lane >> 4) << 3;
#pragma unroll
        for (int kf = 0; kf < 4; kf++) {
            int off = (wid * 16 + ar) * KSP + kf * 16 + acb;
            LDSM4(qfh[kf], sm_addr(&sKH[off]));
            LDSM4(qfl[kf], sm_addr(&sKL[off]));
        }
    }
    __syncthreads();

    float oacc[8][4];
#pragma unroll
    for (int i = 0; i < 8; i++)
#pragma unroll
        for (int q = 0; q < 4; q++) oacc[i][q] = 0.f;
    float m0 = -1e30f, m1 = -1e30f, l0 = 0.f, l1 = 0.f;

    auto loadKV = [&](int st, int s0) {
#pragma unroll
        for (int i = 0; i < 4; i++) {
            int ch = tid + i * 256;
            int row = ch >> 3, c = ch & 7;
            size_t g = (size_t)(s0 + row) * DM + h * 64 + c * 8;
            int so = st * KST + row * KSP + c * 8;
            cpa16(sm_addr(&sKH[so]), kh_g + g);
            cpa16(sm_addr(&sKL[so]), kl_g + g);
        }
#pragma unroll
        for (int i = 0; i < 4; i++) {
            int ch = tid + i * 256;
            int row = ch >> 4, c = ch & 15;
            size_t g = (size_t)(h * 64 + row) * SEQ + s0 + c * 8;
            int so = st * VST + row * VSP + c * 8;
            cpa16(sm_addr(&sVH[so]), vth_g + g);
            cpa16(sm_addr(&sVL[so]), vtl_g + g);
        }
    };

    loadKV(0, 0); CP_COMMIT();
    loadKV(1, 128); CP_COMMIT();

    const int br = (lane < 16) ? (lane & 7) : 8 + (lane & 7);
    const int bcsel = ((lane >> 3) & 1) << 3;

    for (int kt = 0; kt < SEQ / 128; kt++) {
        if (kt < SEQ / 128 - 1) CP_WAIT1(); else CP_WAIT0();
        __syncthreads();
        if (kt + 2 < SEQ / 128) {
            int nx = kt + 2;
            loadKV(nx - (nx / 3) * 3, nx * 128);
            CP_COMMIT();
        }

        const int st = kt - (kt / 3) * 3;
        const bf16* kH = sKH + st * KST;
        const bf16* kL = sKL + st * KST;
        const bf16* vH = sVH + st * VST;
        const bf16* vL = sVL + st * VST;

        float sacc[16][4];
#pragma unroll
        for (int i = 0; i < 16; i++)
#pragma unroll
            for (int q = 0; q < 4; q++) sacc[i][q] = 0.f;

#pragma unroll
        for (int kf = 0; kf < 4; kf++) {
            const int bc = kf * 16 + bcsel;
#pragma unroll
            for (int nn = 0; nn < 16; nn += 2) {
                uint32_t th[4], tl[4];
                LDSM4(th, sm_addr(&kH[(nn * 8 + br) * KSP + bc]));
                LDSM4(tl, sm_addr(&kL[(nn * 8 + br) * KSP + bc]));
                mma16816(sacc[nn], qfh[kf], th);
                mma16816(sacc[nn], qfh[kf], tl);
                mma16816(sacc[nn], qfl[kf], th);
                mma16816(sacc[nn + 1], qfh[kf], th + 2);
                mma16816(sacc[nn + 1], qfh[kf], tl + 2);
                mma16816(sacc[nn + 1], qfl[kf], th + 2);
            }
        }

        // scale + row max (rows gid / gid+8 of this warp's strip)
        float tm0 = -1e30f, tm1 = -1e30f;
#pragma unroll
        for (int nf = 0; nf < 16; nf++) {
            sacc[nf][0] *= 0.125f; sacc[nf][1] *= 0.125f;
            sacc[nf][2] *= 0.125f; sacc[nf][3] *= 0.125f;
            tm0 = fmaxf(tm0, fmaxf(sacc[nf][0], sacc[nf][1]));
            tm1 = fmaxf(tm1, fmaxf(sacc[nf][2], sacc[nf][3]));
        }
        tm0 = fmaxf(tm0, __shfl_xor_sync(0xffffffffu, tm0, 1));
        tm0 = fmaxf(tm0, __shfl_xor_sync(0xffffffffu, tm0, 2));
        tm1 = fmaxf(tm1, __shfl_xor_sync(0xffffffffu, tm1, 1));
        tm1 = fmaxf(tm1, __shfl_xor_sync(0xffffffffu, tm1, 2));

        const float mn0 = fmaxf(m0, tm0), mn1 = fmaxf(m1, tm1);
        const float a0 = __expf(m0 - mn0), a1 = __expf(m1 - mn1);

        float rs0 = 0.f, rs1 = 0.f;
#pragma unroll
        for (int nf = 0; nf < 16; nf++) {
            sacc[nf][0] = __expf(sacc[nf][0] - mn0);
            sacc[nf][1] = __expf(sacc[nf][1] - mn0);
            sacc[nf][2] = __expf(sacc[nf][2] - mn1);
            sacc[nf][3] = __expf(sacc[nf][3] - mn1);
            rs0 += sacc[nf][0] + sacc[nf][1];
            rs1 += sacc[nf][2] + sacc[nf][3];
        }
        rs0 += __shfl_xor_sync(0xffffffffu, rs0, 1);
        rs0 += __shfl_xor_sync(0xffffffffu, rs0, 2);
        rs1 += __shfl_xor_sync(0xffffffffu, rs1, 1);
        rs1 += __shfl_xor_sync(0xffffffffu, rs1, 2);

        m0 = mn0; m1 = mn1;
        l0 = l0 * a0 + rs0;
        l1 = l1 * a1 + rs1;

#pragma unroll
        for (int nf = 0; nf < 8; nf++) {
            oacc[nf][0] *= a0; oacc[nf][1] *= a0;
            oacc[nf][2] *= a1; oacc[nf][3] *= a1;
        }

        // O += P @ V   (P from sacc regs, V^T from smem)
#pragma unroll
        for (int j = 0; j < 8; j++) {
            uint32_t pah[4], pal[4];
            pack_split2(sacc[2 * j][0], sacc[2 * j][1], pah[0], pal[0]);
            pack_split2(sacc[2 * j][2], sacc[2 * j][3], pah[1], pal[1]);
            pack_split2(sacc[2 * j + 1][0], sacc[2 * j + 1][1], pah[2], pal[2]);
            pack_split2(sacc[2 * j + 1][2], sacc[2 * j + 1][3], pah[3], pal[3]);
            const int bc = j * 16 + bcsel;
#pragma unroll
            for (int nn = 0; nn < 8; nn += 2) {
                uint32_t th[4], tl[4];
                LDSM4(th, sm_addr(&vH[(nn * 8 + br) * VSP + bc]));
                LDSM4(tl, sm_addr(&vL[(nn * 8 + br) * VSP + bc]));
                mma16816(oacc[nn], pah, th);
                mma16816(oacc[nn], pah, tl);
                mma16816(oacc[nn], pal, th);
                mma16816(oacc[nn + 1], pah, th + 2);
                mma16816(oacc[nn + 1], pah, tl + 2);
                mma16816(oacc[nn + 1], pal, th + 2);
            }
        }
    }

    // ---- epilogue: O/l, split, store ctx ----
    const float il0 = 1.f / l0, il1 = 1.f / l1;
    const int mA = q0 + wid * 16 + gid;
    const int mB = mA + 8;
#pragma unroll
    for (int nf = 0; nf < 8; nf++) {
        const int col = h * 64 + nf * 8 + 2 * tig;
        uint32_t h01, l01, h23, l23;
        pack_split2(oacc[nf][0] * il0, oacc[nf][1] * il0, h01, l01);
        pack_split2(oacc[nf][2] * il1, oacc[nf][3] * il1, h23, l23);
        *(uint32_t*)(ch_g + (size_t)mA * DM + col) = h01;
        *(uint32_t*)(cl_g + (size_t)mA * DM + col) = l01;
        *(uint32_t*)(ch_g + (size_t)mB * DM + col) = h23;
        *(uint32_t*)(cl_g + (size_t)mB * DM + col) = l23;
    }
}

// ---------------- transpose + split weights: W[R,C] fp32 -> WT[C,R] bf16 hi/lo ----------------
__global__ void trans_split_k(const float* __restrict__ in, bf16* __restrict__ oh,
                              bf16* __restrict__ ol, int R, int C)
{
    __shared__ float t[32][33];
    const size_t zo = (size_t)blockIdx.z * R * C;
    in += zo; oh += zo; ol += zo;
    const int r0 = blockIdx.y * 32, c0 = blockIdx.x * 32;
    const int tx = threadIdx.x, ty = threadIdx.y;
#pragma unroll
    for (int i = 0; i < 32; i += 8)
        t[ty + i][tx] = in[(size_t)(r0 + ty + i) * C + c0 + tx];
    __syncthreads();
#pragma unroll
    for (int i = 0; i < 32; i += 8) {
        float v = t[tx][ty + i];
        bf16 h, l; split_bf(v, h, l);
        size_t o = (size_t)(c0 + ty + i) * R + r0 + tx;
        oh[o] = h; ol[o] = l;
    }
}

// ---------------- transpose two bf16 matrices [R,C] -> [C,R] ----------------
__global__ void trans2_bf16_k(const bf16* __restrict__ a, bf16* __restrict__ at,
                              const bf16* __restrict__ b, bf16* __restrict__ bt,
                              int R, int C)
{
    __shared__ bf16 ta[32][33], tb[32][33];
    const int r0 = blockIdx.y * 32, c0 = blockIdx.x * 32;
    const int tx = threadIdx.x, ty = threadIdx.y;
#pragma unroll
    for (int i = 0; i < 32; i += 8) {
        size_t g = (size_t)(r0 + ty + i) * C + c0 + tx;
        ta[ty + i][tx] = a[g];
        tb[ty + i][tx] = b[g];
    }
    __syncthreads();
#pragma unroll
    for (int i = 0; i < 32; i += 8) {
        size_t o = (size_t)(c0 + ty + i) * R + r0 + tx;
        at[o] = ta[tx][ty + i];
        bt[o] = tb[tx][ty + i];
    }
}

// ---------------- elementwise split ----------------
__global__ void split_k(const float* __restrict__ x, bf16* __restrict__ h,
                        bf16* __restrict__ l, int n)
{
    int i = blockIdx.x * 256 + threadIdx.x;
    if (i < n) {
        bf16 hh, ll; split_bf(x[i], hh, ll);
        h[i] = hh; l[i] = ll;
    }
}

// ---------------- residual + LayerNorm, writes x fp32 and split ----------------
__global__ __launch_bounds__(256) void add_ln_split_k(
    float* __restrict__ x, const float* __restrict__ y,
    const float* __restrict__ g, const float* __restrict__ b,
    bf16* __restrict__ xh, bf16* __restrict__ xl)
{
    __shared__ float r[DM];
    __shared__ float red[256];
    const int tid = threadIdx.x;
    const size_t off = (size_t)blockIdx.x * DM;

    float lsum = 0.f;
    for (int j = tid; j < DM; j += 256) {
        float v = x[off + j] + y[off + j];
        r[j] = v;
        lsum += v;
    }
    red[tid] = lsum; __syncthreads();
    for (int st = 128; st > 0; st >>= 1) {
        if (tid < st) red[tid] += red[tid + st];
        __syncthreads();
    }
    const float mu = red[0] * (1.0f / DM);
    __syncthreads();

    float lv = 0.f;
    for (int j = tid; j < DM; j += 256) {
        float d = r[j] - mu;
        lv += d * d;
    }
    red[tid] = lv; __syncthreads();
    for (int st = 128; st > 0; st >>= 1) {
        if (tid < st) red[tid] += red[tid + st];
        __syncthreads();
    }
    const float rstd = rsqrtf(red[0] * (1.0f / DM) + 1e-5f);

    for (int j = tid; j < DM; j += 256) {
        float v = (r[j] - mu) * rstd * g[j] + b[j];
        x[off + j] = v;
        bf16 h, l; split_bf(v, h, l);
        xh[off + j] = h; xl[off + j] = l;
    }
}

// ---------------- host launch ----------------
static const int SMEMMM = (3 * 128 * 40 * 2 + 3 * 64 * 40 * 2) * 2;  // 92160
static const int SMEMFA = (3 * 128 * 72 * 2 + 3 * 64 * 136 * 2) * 2; // 215040

extern "C" void kernel_launch(void* const* d_in, const int* in_sizes, int n_in,
                              void* d_out, int out_size)
{
    const float* x_in = (const float*)d_in[0];
    const float* wq = (const float*)d_in[1];
    const float* bq = (const float*)d_in[2];
    const float* wk = (const float*)d_in[3];
    const float* bk = (const float*)d_in[4];
    const float* wv = (const float*)d_in[5];
    const float* bv = (const float*)d_in[6];
    const float* wo = (const float*)d_in[7];
    const float* bo = (const float*)d_in[8];
    const float* w1 = (const float*)d_in[9];
    const float* b1 = (const float*)d_in[10];
    const float* w2 = (const float*)d_in[11];
    const float* b2 = (const float*)d_in[12];
    const float* ln1g = (const float*)d_in[13];
    const float* ln1b = (const float*)d_in[14];
    const float* ln2g = (const float*)d_in[15];
    const float* ln2b = (const float*)d_in[16];

    float* x = (float*)d_out;

    bf16 *wqTh, *wqTl, *wkTh, *wkTl, *wvTh, *wvTl, *woTh, *woTl;
    bf16 *w1Th, *w1Tl, *w2Th, *w2Tl;
    bf16 *xh, *xl, *qh, *ql, *kh, *kl, *vh, *vl, *vth, *vtl, *ch, *cl, *hh, *hl;
    float *tmp;
    cudaGetSymbolAddress((void**)&wqTh, g_wqT_h); cudaGetSymbolAddress((void**)&wqTl, g_wqT_l);
    cudaGetSymbolAddress((void**)&wkTh, g_wkT_h); cudaGetSymbolAddress((void**)&wkTl, g_wkT_l);
    cudaGetSymbolAddress((void**)&wvTh, g_wvT_h); cudaGetSymbolAddress((void**)&wvTl, g_wvT_l);
    cudaGetSymbolAddress((void**)&woTh, g_woT_h); cudaGetSymbolAddress((void**)&woTl, g_woT_l);
    cudaGetSymbolAddress((void**)&w1Th, g_w1T_h); cudaGetSymbolAddress((void**)&w1Tl, g_w1T_l);
    cudaGetSymbolAddress((void**)&w2Th, g_w2T_h); cudaGetSymbolAddress((void**)&w2Tl, g_w2T_l);
    cudaGetSymbolAddress((void**)&xh, g_xh); cudaGetSymbolAddress((void**)&xl, g_xl);
    cudaGetSymbolAddress((void**)&qh, g_qh); cudaGetSymbolAddress((void**)&ql, g_ql);
    cudaGetSymbolAddress((void**)&kh, g_kh); cudaGetSymbolAddress((void**)&kl, g_kl);
    cudaGetSymbolAddress((void**)&vh, g_vh); cudaGetSymbolAddress((void**)&vl, g_vl);
    cudaGetSymbolAddress((void**)&vth, g_vth); cudaGetSymbolAddress((void**)&vtl, g_vtl);
    cudaGetSymbolAddress((void**)&ch, g_ch); cudaGetSymbolAddress((void**)&cl, g_cl);
    cudaGetSymbolAddress((void**)&hh, g_hh); cudaGetSymbolAddress((void**)&hl, g_hl);
    cudaGetSymbolAddress((void**)&tmp, g_tmp);

    cudaFuncSetAttribute(mmsync<1>, cudaFuncAttributeMaxDynamicSharedMemorySize, SMEMMM);
    cudaFuncSetAttribute(mmsync<2>, cudaFuncAttributeMaxDynamicSharedMemorySize, SMEMMM);
    cudaFuncSetAttribute(mmsync<4>, cudaFuncAttributeMaxDynamicSharedMemorySize, SMEMMM);
    cudaFuncSetAttribute(flash_attn, cudaFuncAttributeMaxDynamicSharedMemorySize, SMEMFA);

    const dim3 tb(32, 8);
    trans_split_k<<<dim3(DM / 32, DM / 32, NL), tb>>>(wq, wqTh, wqTl, DM, DM);
    trans_split_k<<<dim3(DM / 32, DM / 32, NL), tb>>>(wk, wkTh, wkTl, DM, DM);
    trans_split_k<<<dim3(DM / 32, DM / 32, NL), tb>>>(wv, wvTh, wvTl, DM, DM);
    trans_split_k<<<dim3(DM / 32, DM / 32, NL), tb>>>(wo, woTh, woTl, DM, DM);
    trans_split_k<<<dim3(DFF / 32, DM / 32, NL), tb>>>(w1, w1Th, w1Tl, DM, DFF);
    trans_split_k<<<dim3(DM / 32, DFF / 32, NL), tb>>>(w2, w2Th, w2Tl, DFF, DM);

    cudaMemcpyAsync(x, x_in, (size_t)SEQ * DM * sizeof(float), cudaMemcpyDeviceToDevice);
    split_k<<<(SEQ * DM) / 256, 256>>>(x_in, xh, xl, SEQ * DM);

    const dim3 gP(DM / 64, SEQ / 128);        // (16,16)
    const dim3 gFA(NH, SEQ / 128);            // (16,16)
    const dim3 gF1(DFF / 64, SEQ / 128);      // (64,16)

    for (int l = 0; l < NL; l++) {
        const size_t lW = (size_t)l * DM * DM;
        const size_t lF = (size_t)l * DM * DFF;

        mmsync<2><<<gP, 256, SMEMMM>>>(xh, xl, wqTh + lW, wqTl + lW, bq + l * DM,
            nullptr, qh, ql, DM, DM, DM, DM);
        mmsync<2><<<gP, 256, SMEMMM>>>(xh, xl, wkTh + lW, wkTl + lW, bk + l * DM,
            nullptr, kh, kl, DM, DM, DM, DM);
        mmsync<2><<<gP, 256, SMEMMM>>>(xh, xl, wvTh + lW, wvTl + lW, bv + l * DM,
            nullptr, vh, vl, DM, DM, DM, DM);
        trans2_bf16_k<<<dim3(DM / 32, SEQ / 32), tb>>>(vh, vth, vl, vtl, SEQ, DM);

        // fused attention: scores + softmax + AV
        flash_attn<<<gFA, 256, SMEMFA>>>(qh, ql, kh, kl, vth, vtl, ch, cl);

        mmsync<1><<<gP, 256, SMEMMM>>>(ch, cl, woTh + lW, woTl + lW, bo + l * DM,
            tmp, nullptr, nullptr, DM, DM, DM, DM);

        add_ln_split_k<<<SEQ, 256>>>(x, tmp, ln1g + l * DM, ln1b + l * DM, xh, xl);

        mmsync<4><<<gF1, 256, SMEMMM>>>(xh, xl, w1Th + lF, w1Tl + lF, b1 + l * DFF,
            nullptr, hh, hl, DM, DM, DM, DFF);

        mmsync<1><<<gP, 256, SMEMMM>>>(hh, hl, w2Th + lF, w2Tl + lF, b2 + l * DM,
            tmp, nullptr, nullptr, DFF, DFF, DFF, DM);

        add_ln_split_k<<<SEQ, 256>>>(x, tmp, ln2g + l * DM, ln2b + l * DM, xh, xl);
    }
}

// round 10
// speedup vs baseline: 1.4969x; 1.4969x over previous
#include <cuda_runtime.h>
#include <cuda_bf16.h>
#include <math.h>
#include <stdint.h>

#define SEQ 2048
#define DM  1024
#define NH  16
#define DK  64
#define DFF 4096
#define NL  4

typedef __nv_bfloat16 bf16;

// ---------------- device scratch (no cudaMalloc allowed) ----------------
__device__ bf16 g_wqT_h[NL * DM * DM], g_wqT_l[NL * DM * DM];
__device__ bf16 g_wkT_h[NL * DM * DM], g_wkT_l[NL * DM * DM];
__device__ bf16 g_wvT_h[NL * DM * DM], g_wvT_l[NL * DM * DM];
__device__ bf16 g_woT_h[NL * DM * DM], g_woT_l[NL * DM * DM];
__device__ bf16 g_w1T_h[NL * DM * DFF], g_w1T_l[NL * DM * DFF];
__device__ bf16 g_w2T_h[NL * DM * DFF], g_w2T_l[NL * DM * DFF];
__device__ bf16 g_xh[SEQ * DM], g_xl[SEQ * DM];
__device__ bf16 g_qh[SEQ * DM], g_ql[SEQ * DM];
__device__ bf16 g_kh[SEQ * DM], g_kl[SEQ * DM];
__device__ bf16 g_vh[SEQ * DM], g_vl[SEQ * DM];
__device__ bf16 g_vth[DM * SEQ], g_vtl[DM * SEQ];   // V^T
__device__ bf16 g_ch[SEQ * DM], g_cl[SEQ * DM];
__device__ bf16 g_hh[SEQ * DFF], g_hl[SEQ * DFF];
__device__ float g_tmp[SEQ * DM];

// ---------------- small helpers ----------------
__device__ __forceinline__ float gelu_f(float v) {
    return 0.5f * v * (1.0f + tanhf(0.7978845608028654f * (v + 0.044715f * v * v * v)));
}
__device__ __forceinline__ void split_bf(float v, bf16& h, bf16& l) {
    h = __float2bfloat16(v);
    l = __float2bfloat16(v - __bfloat162float(h));
}
__device__ __forceinline__ void cpa16(uint32_t dst, const void* src) {
    asm volatile("cp.async.cg.shared.global [%0], [%1], 16;" :: "r"(dst), "l"(src));
}
#define CP_COMMIT() asm volatile("cp.async.commit_group;" ::: "memory")
#define CP_WAIT0()  asm volatile("cp.async.wait_group 0;" ::: "memory")
#define CP_WAIT1()  asm volatile("cp.async.wait_group 1;" ::: "memory")
#define LDSM4(r, a) asm volatile( \
    "ldmatrix.sync.aligned.m8n8.x4.shared.b16 {%0,%1,%2,%3}, [%4];" \
    : "=r"((r)[0]), "=r"((r)[1]), "=r"((r)[2]), "=r"((r)[3]) : "r"(a))

__device__ __forceinline__ void mma16816(float* c, const uint32_t* a, const uint32_t* b) {
    asm volatile(
        "mma.sync.aligned.m16n8k16.row.col.f32.bf16.bf16.f32 "
        "{%0,%1,%2,%3}, {%4,%5,%6,%7}, {%8,%9}, {%0,%1,%2,%3};"
        : "+f"(c[0]), "+f"(c[1]), "+f"(c[2]), "+f"(c[3])
        : "r"(a[0]), "r"(a[1]), "r"(a[2]), "r"(a[3]), "r"(b[0]), "r"(b[1]));
}
__device__ __forceinline__ uint32_t sm_addr(const void* p) {
    return (uint32_t)__cvta_generic_to_shared(p);
}
__device__ __forceinline__ void pack_split2(float x, float y, uint32_t& h, uint32_t& l) {
    __nv_bfloat162 hh, ll;
    hh.x = __float2bfloat16(x); ll.x = __float2bfloat16(x - __bfloat162float(hh.x));
    hh.y = __float2bfloat16(y); ll.y = __float2bfloat16(y - __bfloat162float(hh.y));
    h = *(uint32_t*)&hh; l = *(uint32_t*)&ll;
}

// ---------------- mma.sync GEMM: 128x128 tile, 3-stage, 1 barrier/K-tile ----------------
// D[128, 128] tile of (A @ B^T) [+bias][gelu]; A,B split hi/lo, K-contiguous.
// EPI: 1 f32+bias, 2 split+bias, 4 gelu(v+bias) split
template <int EPI>
__global__ __launch_bounds__(256) void mmsync(
    const bf16* __restrict__ Ah, const bf16* __restrict__ Al,
    const bf16* __restrict__ Bh, const bf16* __restrict__ Bl,
    const float* __restrict__ bias,
    float* __restrict__ Cf, bf16* __restrict__ Ch, bf16* __restrict__ Cl,
    int K, int lda, int ldb, int ldc)
{
    constexpr int SP  = 40;                // padded row stride (halfs) for BK=32
    constexpr int AST = 128 * SP;          // stage size (halfs), A and B identical
    constexpr int MF  = 4;                 // warp tile 64x32
    constexpr int NF  = 4;

    extern __shared__ bf16 sm[];
    bf16* sAH = sm;                        // 3 * AST each
    bf16* sAL = sAH + 3 * AST;
    bf16* sBH = sAL + 3 * AST;
    bf16* sBL = sBH + 3 * AST;

    const int tid = threadIdx.x;
    const int wid = tid >> 5;
    const int lane = tid & 31;
    const int gid = lane >> 2, tig = lane & 3;
    const int bm = blockIdx.y * 128;
    const int bn = blockIdx.x * 128;

    const int wm0 = (wid >> 2) * 64;       // 2 warp-rows x 4 warp-cols
    const int wn0 = (wid & 3) * 32;

    float acc[MF][NF][4];
#pragma unroll
    for (int i = 0; i < MF; i++)
#pragma unroll
        for (int j = 0; j < NF; j++)
#pragma unroll
            for (int q = 0; q < 4; q++) acc[i][j][q] = 0.f;

    const int nk = K >> 5;

    auto loadStage = [&](int st, int k0) {
#pragma unroll
        for (int i = 0; i < 2; i++) {
            int ch = tid + i * 256;        // 512 chunks: row = ch/4, c = ch%4
            int row = ch >> 2, c = ch & 3;
            size_t ga = (size_t)(bm + row) * lda + k0 + c * 8;
            size_t gb = (size_t)(bn + row) * ldb + k0 + c * 8;
            int so = st * AST + row * SP + c * 8;
            cpa16(sm_addr(&sAH[so]), Ah + ga);
            cpa16(sm_addr(&sAL[so]), Al + ga);
            cpa16(sm_addr(&sBH[so]), Bh + gb);
            cpa16(sm_addr(&sBL[so]), Bl + gb);
        }
    };

    loadStage(0, 0); CP_COMMIT();
    loadStage(1, 32); CP_COMMIT();

    const int ar = lane & 15;
    const int acb = (lane >> 4) << 3;
    const int br = (lane < 16) ? (lane & 7) : 8 + (lane & 7);
    const int bcsel = ((lane >> 3) & 1) << 3;

    for (int kt = 0; kt < nk; kt++) {
        if (kt < nk - 1) CP_WAIT1(); else CP_WAIT0();
        __syncthreads();
        if (kt + 2 < nk) {
            int nx = kt + 2;
            loadStage(nx - (nx / 3) * 3, nx << 5);
            CP_COMMIT();
        }

        const int st = kt - (kt / 3) * 3;
        const bf16* aH = sAH + st * AST;
        const bf16* aL = sAL + st * AST;
        const bf16* bH = sBH + st * AST;
        const bf16* bL = sBL + st * AST;

#pragma unroll
        for (int kk = 0; kk < 2; kk++) {
            const int koff = kk * 16;
            uint32_t ah[MF][4], al[MF][4];
#pragma unroll
            for (int mf = 0; mf < MF; mf++) {
                int r = wm0 + mf * 16 + ar;
                LDSM4(ah[mf], sm_addr(&aH[r * SP + koff + acb]));
                LDSM4(al[mf], sm_addr(&aL[r * SP + koff + acb]));
            }
            uint32_t bh[NF][2], bl[NF][2];
            const int bc = koff + bcsel;
#pragma unroll
            for (int nn = 0; nn < NF; nn += 2) {
                int r = wn0 + nn * 8 + br;
                uint32_t t[4];
                LDSM4(t, sm_addr(&bH[r * SP + bc]));
                bh[nn][0] = t[0]; bh[nn][1] = t[1];
                bh[nn + 1][0] = t[2]; bh[nn + 1][1] = t[3];
                LDSM4(t, sm_addr(&bL[r * SP + bc]));
                bl[nn][0] = t[0]; bl[nn][1] = t[1];
                bl[nn + 1][0] = t[2]; bl[nn + 1][1] = t[3];
            }
#pragma unroll
            for (int mf = 0; mf < MF; mf++)
#pragma unroll
                for (int nf = 0; nf < NF; nf++) {
                    mma16816(acc[mf][nf], ah[mf], bh[nf]);
                    mma16816(acc[mf][nf], ah[mf], bl[nf]);
                    mma16816(acc[mf][nf], al[mf], bh[nf]);
                }
        }
    }

    // ---------------- epilogue ----------------
#pragma unroll
    for (int mf = 0; mf < MF; mf++) {
        const int mA = bm + wm0 + mf * 16 + gid;
        const int mB = mA + 8;
#pragma unroll
        for (int nf = 0; nf < NF; nf++) {
            const int n = bn + wn0 + nf * 8 + 2 * tig;
            float c0 = acc[mf][nf][0], c1 = acc[mf][nf][1];
            float c2 = acc[mf][nf][2], c3 = acc[mf][nf][3];
            float b0 = bias[n], b1 = bias[n + 1];
            if (EPI == 1) {
                float2 u = make_float2(c0 + b0, c1 + b1);
                float2 w = make_float2(c2 + b0, c3 + b1);
                *(float2*)(Cf + (size_t)mA * ldc + n) = u;
                *(float2*)(Cf + (size_t)mB * ldc + n) = w;
            } else {
                float v0 = c0 + b0, v1 = c1 + b1, v2 = c2 + b0, v3 = c3 + b1;
                if (EPI == 4) {
                    v0 = gelu_f(v0); v1 = gelu_f(v1);
                    v2 = gelu_f(v2); v3 = gelu_f(v3);
                }
                uint32_t h01, l01, h23, l23;
                pack_split2(v0, v1, h01, l01);
                pack_split2(v2, v3, h23, l23);
                *(uint32_t*)(Ch + (size_t)mA * ldc + n) = h01;
                *(uint32_t*)(Cl + (size_t)mA * ldc + n) = l01;
                *(uint32_t*)(Ch + (size_t)mB * ldc + n) = h23;
                *(uint32_t*)(Cl + (size_t)mB * ldc + n) = l23;
            }
        }
    }
}

// ---------------- flash attention: S=QK^T/8, online softmax, O=PV ----------------
// grid (NH, SEQ/128), 256 threads (8 warps x 16 q-rows), 3-stage KV pipeline
__global__ __launch_bounds__(256) void flash_attn(
    const bf16* __restrict__ qh_g, const bf16* __restrict__ ql_g,
    const bf16* __restrict__ kh_g, const bf16* __restrict__ kl_g,
    const bf16* __restrict__ vth_g, const bf16* __restrict__ vtl_g,
    bf16* __restrict__ ch_g, bf16* __restrict__ cl_g)
{
    constexpr int KSP = 72, VSP = 136;
    constexpr int KST = 128 * KSP;
    constexpr int VST = 64 * VSP;
    const int h = blockIdx.x;
    const int q0 = blockIdx.y * 128;
    const int tid = threadIdx.x, wid = tid >> 5, lane = tid & 31;
    const int gid = lane >> 2, tig = lane & 3;

    extern __shared__ bf16 sm[];
    bf16* sKH = sm;                        // 3 * KST
    bf16* sKL = sKH + 3 * KST;
    bf16* sVH = sKL + 3 * KST;             // 3 * VST
    bf16* sVL = sVH + 3 * VST;

    // ---- prologue: Q tile into stage-0 K buffers, extract frags ----
#pragma unroll
    for (int i = 0; i < 4; i++) {
        int ch = tid + i * 256;
        int row = ch >> 3, c = ch & 7;
        size_t g = (size_t)(q0 + row) * DM + h * 64 + c * 8;
        cpa16(sm_addr(&sKH[row * KSP + c * 8]), qh_g + g);
        cpa16(sm_addr(&sKL[row * KSP + c * 8]), ql_g + g);
    }
    CP_COMMIT(); CP_WAIT0();
    __syncthreads();

    uint32_t qfh[4][4], qfl[4][4];
    {
        const int ar = lane & 15, acb = (lane >> 4) << 3;
#pragma unroll
        for (int kf = 0; kf < 4; kf++) {
            int off = (wid * 16 + ar) * KSP + kf * 16 + acb;
            LDSM4(qfh[kf], sm_addr(&sKH[off]));
            LDSM4(qfl[kf], sm_addr(&sKL[off]));
        }
    }
    __syncthreads();

    float oacc[8][4];
#pragma unroll
    for (int i = 0; i < 8; i++)
#pragma unroll
        for (int q = 0; q < 4; q++) oacc[i][q] = 0.f;
    float m0 = -1e30f, m1 = -1e30f, l0 = 0.f, l1 = 0.f;

    auto loadKV = [&](int st, int s0) {
#pragma unroll
        for (int i = 0; i < 4; i++) {
            int ch = tid + i * 256;
            int row = ch >> 3, c = ch & 7;
            size_t g = (size_t)(s0 + row) * DM + h * 64 + c * 8;
            int so = st * KST + row * KSP + c * 8;
            cpa16(sm_addr(&sKH[so]), kh_g + g);
            cpa16(sm_addr(&sKL[so]), kl_g + g);
        }
#pragma unroll
        for (int i = 0; i < 4; i++) {
            int ch = tid + i * 256;
            int row = ch >> 4, c = ch & 15;
            size_t g = (size_t)(h * 64 + row) * SEQ + s0 + c * 8;
            int so = st * VST + row * VSP + c * 8;
            cpa16(sm_addr(&sVH[so]), vth_g + g);
            cpa16(sm_addr(&sVL[so]), vtl_g + g);
        }
    };

    loadKV(0, 0); CP_COMMIT();
    loadKV(1, 128); CP_COMMIT();

    const int br = (lane < 16) ? (lane & 7) : 8 + (lane & 7);
    const int bcsel = ((lane >> 3) & 1) << 3;

    for (int kt = 0; kt < SEQ / 128; kt++) {
        if (kt < SEQ / 128 - 1) CP_WAIT1(); else CP_WAIT0();
        __syncthreads();
        if (kt + 2 < SEQ / 128) {
            int nx = kt + 2;
            loadKV(nx - (nx / 3) * 3, nx * 128);
            CP_COMMIT();
        }

        const int st = kt - (kt / 3) * 3;
        const bf16* kH = sKH + st * KST;
        const bf16* kL = sKL + st * KST;
        const bf16* vH = sVH + st * VST;
        const bf16* vL = sVL + st * VST;

        float sacc[16][4];
#pragma unroll
        for (int i = 0; i < 16; i++)
#pragma unroll
            for (int q = 0; q < 4; q++) sacc[i][q] = 0.f;

#pragma unroll
        for (int kf = 0; kf < 4; kf++) {
            const int bc = kf * 16 + bcsel;
#pragma unroll
            for (int nn = 0; nn < 16; nn += 2) {
                uint32_t th[4], tl[4];
                LDSM4(th, sm_addr(&kH[(nn * 8 + br) * KSP + bc]));
                LDSM4(tl, sm_addr(&kL[(nn * 8 + br) * KSP + bc]));
                mma16816(sacc[nn], qfh[kf], th);
                mma16816(sacc[nn], qfh[kf], tl);
                mma16816(sacc[nn], qfl[kf], th);
                mma16816(sacc[nn + 1], qfh[kf], th + 2);
                mma16816(sacc[nn + 1], qfh[kf], tl + 2);
                mma16816(sacc[nn + 1], qfl[kf], th + 2);
            }
        }

        // scale + row max (rows gid / gid+8 of this warp's strip)
        float tm0 = -1e30f, tm1 = -1e30f;
#pragma unroll
        for (int nf = 0; nf < 16; nf++) {
            sacc[nf][0] *= 0.125f; sacc[nf][1] *= 0.125f;
            sacc[nf][2] *= 0.125f; sacc[nf][3] *= 0.125f;
            tm0 = fmaxf(tm0, fmaxf(sacc[nf][0], sacc[nf][1]));
            tm1 = fmaxf(tm1, fmaxf(sacc[nf][2], sacc[nf][3]));
        }
        tm0 = fmaxf(tm0, __shfl_xor_sync(0xffffffffu, tm0, 1));
        tm0 = fmaxf(tm0, __shfl_xor_sync(0xffffffffu, tm0, 2));
        tm1 = fmaxf(tm1, __shfl_xor_sync(0xffffffffu, tm1, 1));
        tm1 = fmaxf(tm1, __shfl_xor_sync(0xffffffffu, tm1, 2));

        const float mn0 = fmaxf(m0, tm0), mn1 = fmaxf(m1, tm1);
        const float a0 = __expf(m0 - mn0), a1 = __expf(m1 - mn1);

        float rs0 = 0.f, rs1 = 0.f;
#pragma unroll
        for (int nf = 0; nf < 16; nf++) {
            sacc[nf][0] = __expf(sacc[nf][0] - mn0);
            sacc[nf][1] = __expf(sacc[nf][1] - mn0);
            sacc[nf][2] = __expf(sacc[nf][2] - mn1);
            sacc[nf][3] = __expf(sacc[nf][3] - mn1);
            rs0 += sacc[nf][0] + sacc[nf][1];
            rs1 += sacc[nf][2] + sacc[nf][3];
        }
        rs0 += __shfl_xor_sync(0xffffffffu, rs0, 1);
        rs0 += __shfl_xor_sync(0xffffffffu, rs0, 2);
        rs1 += __shfl_xor_sync(0xffffffffu, rs1, 1);
        rs1 += __shfl_xor_sync(0xffffffffu, rs1, 2);

        m0 = mn0; m1 = mn1;
        l0 = l0 * a0 + rs0;
        l1 = l1 * a1 + rs1;

#pragma unroll
        for (int nf = 0; nf < 8; nf++) {
            oacc[nf][0] *= a0; oacc[nf][1] *= a0;
            oacc[nf][2] *= a1; oacc[nf][3] *= a1;
        }

        // O += P @ V   (P from sacc regs, V^T from smem)
#pragma unroll
        for (int j = 0; j < 8; j++) {
            uint32_t pah[4], pal[4];
            pack_split2(sacc[2 * j][0], sacc[2 * j][1], pah[0], pal[0]);
            pack_split2(sacc[2 * j][2], sacc[2 * j][3], pah[1], pal[1]);
            pack_split2(sacc[2 * j + 1][0], sacc[2 * j + 1][1], pah[2], pal[2]);
            pack_split2(sacc[2 * j + 1][2], sacc[2 * j + 1][3], pah[3], pal[3]);
            const int bc = j * 16 + bcsel;
#pragma unroll
            for (int nn = 0; nn < 8; nn += 2) {
                uint32_t th[4], tl[4];
                LDSM4(th, sm_addr(&vH[(nn * 8 + br) * VSP + bc]));
                LDSM4(tl, sm_addr(&vL[(nn * 8 + br) * VSP + bc]));
                mma16816(oacc[nn], pah, th);
                mma16816(oacc[nn], pah, tl);
                mma16816(oacc[nn], pal, th);
                mma16816(oacc[nn + 1], pah, th + 2);
                mma16816(oacc[nn + 1], pah, tl + 2);
                mma16816(oacc[nn + 1], pal, th + 2);
            }
        }
    }

    // ---- epilogue: O/l, split, store ctx ----
    const float il0 = 1.f / l0, il1 = 1.f / l1;
    const int mA = q0 + wid * 16 + gid;
    const int mB = mA + 8;
#pragma unroll
    for (int nf = 0; nf < 8; nf++) {
        const int col = h * 64 + nf * 8 + 2 * tig;
        uint32_t h01, l01, h23, l23;
        pack_split2(oacc[nf][0] * il0, oacc[nf][1] * il0, h01, l01);
        pack_split2(oacc[nf][2] * il1, oacc[nf][3] * il1, h23, l23);
        *(uint32_t*)(ch_g + (size_t)mA * DM + col) = h01;
        *(uint32_t*)(cl_g + (size_t)mA * DM + col) = l01;
        *(uint32_t*)(ch_g + (size_t)mB * DM + col) = h23;
        *(uint32_t*)(cl_g + (size_t)mB * DM + col) = l23;
    }
}

// ---------------- transpose + split weights: W[R,C] fp32 -> WT[C,R] bf16 hi/lo ----------------
__global__ void trans_split_k(const float* __restrict__ in, bf16* __restrict__ oh,
                              bf16* __restrict__ ol, int R, int C)
{
    __shared__ float t[32][33];
    const size_t zo = (size_t)blockIdx.z * R * C;
    in += zo; oh += zo; ol += zo;
    const int r0 = blockIdx.y * 32, c0 = blockIdx.x * 32;
    const int tx = threadIdx.x, ty = threadIdx.y;
#pragma unroll
    for (int i = 0; i < 32; i += 8)
        t[ty + i][tx] = in[(size_t)(r0 + ty + i) * C + c0 + tx];
    __syncthreads();
#pragma unroll
    for (int i = 0; i < 32; i += 8) {
        float v = t[tx][ty + i];
        bf16 h, l; split_bf(v, h, l);
        size_t o = (size_t)(c0 + ty + i) * R + r0 + tx;
        oh[o] = h; ol[o] = l;
    }
}

// ---------------- transpose two bf16 matrices [R,C] -> [C,R] ----------------
__global__ void trans2_bf16_k(const bf16* __restrict__ a, bf16* __restrict__ at,
                              const bf16* __restrict__ b, bf16* __restrict__ bt,
                              int R, int C)
{
    __shared__ bf16 ta[32][33], tb[32][33];
    const int r0 = blockIdx.y * 32, c0 = blockIdx.x * 32;
    const int tx = threadIdx.x, ty = threadIdx.y;
#pragma unroll
    for (int i = 0; i < 32; i += 8) {
        size_t g = (size_t)(r0 + ty + i) * C + c0 + tx;
        ta[ty + i][tx] = a[g];
        tb[ty + i][tx] = b[g];
    }
    __syncthreads();
#pragma unroll
    for (int i = 0; i < 32; i += 8) {
        size_t o = (size_t)(c0 + ty + i) * R + r0 + tx;
        at[o] = ta[tx][ty + i];
        bt[o] = tb[tx][ty + i];
    }
}

// ---------------- elementwise split ----------------
__global__ void split_k(const float* __restrict__ x, bf16* __restrict__ h,
                        bf16* __restrict__ l, int n)
{
    int i = blockIdx.x * 256 + threadIdx.x;
    if (i < n) {
        bf16 hh, ll; split_bf(x[i], hh, ll);
        h[i] = hh; l[i] = ll;
    }
}

// ---------------- residual + LayerNorm, writes x fp32 and split ----------------
__global__ __launch_bounds__(256) void add_ln_split_k(
    float* __restrict__ x, const float* __restrict__ y,
    const float* __restrict__ g, const float* __restrict__ b,
    bf16* __restrict__ xh, bf16* __restrict__ xl)
{
    __shared__ float r[DM];
    __shared__ float red[256];
    const int tid = threadIdx.x;
    const size_t off = (size_t)blockIdx.x * DM;

    float lsum = 0.f;
    for (int j = tid; j < DM; j += 256) {
        float v = x[off + j] + y[off + j];
        r[j] = v;
        lsum += v;
    }
    red[tid] = lsum; __syncthreads();
    for (int st = 128; st > 0; st >>= 1) {
        if (tid < st) red[tid] += red[tid + st];
        __syncthreads();
    }
    const float mu = red[0] * (1.0f / DM);
    __syncthreads();

    float lv = 0.f;
    for (int j = tid; j < DM; j += 256) {
        float d = r[j] - mu;
        lv += d * d;
    }
    red[tid] = lv; __syncthreads();
    for (int st = 128; st > 0; st >>= 1) {
        if (tid < st) red[tid] += red[tid + st];
        __syncthreads();
    }
    const float rstd = rsqrtf(red[0] * (1.0f / DM) + 1e-5f);

    for (int j = tid; j < DM; j += 256) {
        float v = (r[j] - mu) * rstd * g[j] + b[j];
        x[off + j] = v;
        bf16 h, l; split_bf(v, h, l);
        xh[off + j] = h; xl[off + j] = l;
    }
}

// ---------------- host launch ----------------
static const int SMEMMM = 4 * 3 * 128 * 40 * 2;                      // 122880
static const int SMEMFA = (3 * 128 * 72 * 2 + 3 * 64 * 136 * 2) * 2; // 215040

extern "C" void kernel_launch(void* const* d_in, const int* in_sizes, int n_in,
                              void* d_out, int out_size)
{
    const float* x_in = (const float*)d_in[0];
    const float* wq = (const float*)d_in[1];
    const float* bq = (const float*)d_in[2];
    const float* wk = (const float*)d_in[3];
    const float* bk = (const float*)d_in[4];
    const float* wv = (const float*)d_in[5];
    const float* bv = (const float*)d_in[6];
    const float* wo = (const float*)d_in[7];
    const float* bo = (const float*)d_in[8];
    const float* w1 = (const float*)d_in[9];
    const float* b1 = (const float*)d_in[10];
    const float* w2 = (const float*)d_in[11];
    const float* b2 = (const float*)d_in[12];
    const float* ln1g = (const float*)d_in[13];
    const float* ln1b = (const float*)d_in[14];
    const float* ln2g = (const float*)d_in[15];
    const float* ln2b = (const float*)d_in[16];

    float* x = (float*)d_out;

    bf16 *wqTh, *wqTl, *wkTh, *wkTl, *wvTh, *wvTl, *woTh, *woTl;
    bf16 *w1Th, *w1Tl, *w2Th, *w2Tl;
    bf16 *xh, *xl, *qh, *ql, *kh, *kl, *vh, *vl, *vth, *vtl, *ch, *cl, *hh, *hl;
    float *tmp;
    cudaGetSymbolAddress((void**)&wqTh, g_wqT_h); cudaGetSymbolAddress((void**)&wqTl, g_wqT_l);
    cudaGetSymbolAddress((void**)&wkTh, g_wkT_h); cudaGetSymbolAddress((void**)&wkTl, g_wkT_l);
    cudaGetSymbolAddress((void**)&wvTh, g_wvT_h); cudaGetSymbolAddress((void**)&wvTl, g_wvT_l);
    cudaGetSymbolAddress((void**)&woTh, g_woT_h); cudaGetSymbolAddress((void**)&woTl, g_woT_l);
    cudaGetSymbolAddress((void**)&w1Th, g_w1T_h); cudaGetSymbolAddress((void**)&w1Tl, g_w1T_l);
    cudaGetSymbolAddress((void**)&w2Th, g_w2T_h); cudaGetSymbolAddress((void**)&w2Tl, g_w2T_l);
    cudaGetSymbolAddress((void**)&xh, g_xh); cudaGetSymbolAddress((void**)&xl, g_xl);
    cudaGetSymbolAddress((void**)&qh, g_qh); cudaGetSymbolAddress((void**)&ql, g_ql);
    cudaGetSymbolAddress((void**)&kh, g_kh); cudaGetSymbolAddress((void**)&kl, g_kl);
    cudaGetSymbolAddress((void**)&vh, g_vh); cudaGetSymbolAddress((void**)&vl, g_vl);
    cudaGetSymbolAddress((void**)&vth, g_vth); cudaGetSymbolAddress((void**)&vtl, g_vtl);
    cudaGetSymbolAddress((void**)&ch, g_ch); cudaGetSymbolAddress((void**)&cl, g_cl);
    cudaGetSymbolAddress((void**)&hh, g_hh); cudaGetSymbolAddress((void**)&hl, g_hl);
    cudaGetSymbolAddress((void**)&tmp, g_tmp);

    cudaFuncSetAttribute(mmsync<1>, cudaFuncAttributeMaxDynamicSharedMemorySize, SMEMMM);
    cudaFuncSetAttribute(mmsync<2>, cudaFuncAttributeMaxDynamicSharedMemorySize, SMEMMM);
    cudaFuncSetAttribute(mmsync<4>, cudaFuncAttributeMaxDynamicSharedMemorySize, SMEMMM);
    cudaFuncSetAttribute(flash_attn, cudaFuncAttributeMaxDynamicSharedMemorySize, SMEMFA);

    const dim3 tb(32, 8);
    trans_split_k<<<dim3(DM / 32, DM / 32, NL), tb>>>(wq, wqTh, wqTl, DM, DM);
    trans_split_k<<<dim3(DM / 32, DM / 32, NL), tb>>>(wk, wkTh, wkTl, DM, DM);
    trans_split_k<<<dim3(DM / 32, DM / 32, NL), tb>>>(wv, wvTh, wvTl, DM, DM);
    trans_split_k<<<dim3(DM / 32, DM / 32, NL), tb>>>(wo, woTh, woTl, DM, DM);
    trans_split_k<<<dim3(DFF / 32, DM / 32, NL), tb>>>(w1, w1Th, w1Tl, DM, DFF);
    trans_split_k<<<dim3(DM / 32, DFF / 32, NL), tb>>>(w2, w2Th, w2Tl, DFF, DM);

    cudaMemcpyAsync(x, x_in, (size_t)SEQ * DM * sizeof(float), cudaMemcpyDeviceToDevice);
    split_k<<<(SEQ * DM) / 256, 256>>>(x_in, xh, xl, SEQ * DM);

    const dim3 gP(DM / 128, SEQ / 128);       // (8,16)
    const dim3 gFA(NH, SEQ / 128);            // (16,16)
    const dim3 gF1(DFF / 128, SEQ / 128);     // (32,16)

    for (int l = 0; l < NL; l++) {
        const size_t lW = (size_t)l * DM * DM;
        const size_t lF = (size_t)l * DM * DFF;

        mmsync<2><<<gP, 256, SMEMMM>>>(xh, xl, wqTh + lW, wqTl + lW, bq + l * DM,
            nullptr, qh, ql, DM, DM, DM, DM);
        mmsync<2><<<gP, 256, SMEMMM>>>(xh, xl, wkTh + lW, wkTl + lW, bk + l * DM,
            nullptr, kh, kl, DM, DM, DM, DM);
        mmsync<2><<<gP, 256, SMEMMM>>>(xh, xl, wvTh + lW, wvTl + lW, bv + l * DM,
            nullptr, vh, vl, DM, DM, DM, DM);
        trans2_bf16_k<<<dim3(DM / 32, SEQ / 32), tb>>>(vh, vth, vl, vtl, SEQ, DM);

        // fused attention: scores + softmax + AV
        flash_attn<<<gFA, 256, SMEMFA>>>(qh, ql, kh, kl, vth, vtl, ch, cl);

        mmsync<1><<<gP, 256, SMEMMM>>>(ch, cl, woTh + lW, woTl + lW, bo + l * DM,
            tmp, nullptr, nullptr, DM, DM, DM, DM);

        add_ln_split_k<<<SEQ, 256>>>(x, tmp, ln1g + l * DM, ln1b + l * DM, xh, xl);

        mmsync<4><<<gF1, 256, SMEMMM>>>(xh, xl, w1Th + lF, w1Tl + lF, b1 + l * DFF,
            nullptr, hh, hl, DM, DM, DM, DFF);

        mmsync<1><<<gP, 256, SMEMMM>>>(hh, hl, w2Th + lF, w2Tl + lF, b2 + l * DM,
            tmp, nullptr, nullptr, DFF, DFF, DFF, DM);

        add_ln_split_k<<<SEQ, 256>>>(x, tmp, ln2g + l * DM, ln2b + l * DM, xh, xl);
    }
}

// round 11
// speedup vs baseline: 2.0528x; 1.3714x over previous
#include <cuda_runtime.h>
#include <cuda_fp16.h>
#include <math.h>
#include <stdint.h>

#define SEQ 2048
#define DM  1024
#define NH  16
#define DK  64
#define DFF 4096
#define NL  4

typedef __half h16;

// ---------------- device scratch (no cudaMalloc allowed) ----------------
__device__ h16 g_wqT_h[NL * DM * DM], g_wqT_l[NL * DM * DM];
__device__ h16 g_wkT_h[NL * DM * DM], g_wkT_l[NL * DM * DM];
__device__ h16 g_wvT_h[NL * DM * DM], g_wvT_l[NL * DM * DM];
__device__ h16 g_woT_h[NL * DM * DM], g_woT_l[NL * DM * DM];
__device__ h16 g_w1T_h[NL * DM * DFF], g_w1T_l[NL * DM * DFF];
__device__ h16 g_w2T_h[NL * DM * DFF], g_w2T_l[NL * DM * DFF];
__device__ h16 g_xh[SEQ * DM];
__device__ h16 g_qh[SEQ * DM];
__device__ h16 g_kh[SEQ * DM], g_kl[SEQ * DM];
__device__ h16 g_vh[SEQ * DM], g_vl[SEQ * DM];
__device__ h16 g_vth[DM * SEQ], g_vtl[DM * SEQ];   // V^T hi/lo
__device__ h16 g_ch[SEQ * DM];
__device__ h16 g_hh[SEQ * DFF];
__device__ float g_tmp[SEQ * DM];

// ---------------- small helpers ----------------
__device__ __forceinline__ float gelu_f(float v) {
    return 0.5f * v * (1.0f + tanhf(0.7978845608028654f * (v + 0.044715f * v * v * v)));
}
__device__ __forceinline__ void split_h(float v, h16& h, h16& l) {
    h = __float2half_rn(v);
    l = __float2half_rn(v - __half2float(h));
}
__device__ __forceinline__ uint32_t pack2h(float x, float y) {
    __half2 p = __floats2half2_rn(x, y);
    return *(uint32_t*)&p;
}
__device__ __forceinline__ void cpa16(uint32_t dst, const void* src) {
    asm volatile("cp.async.cg.shared.global [%0], [%1], 16;" :: "r"(dst), "l"(src));
}
#define CP_COMMIT() asm volatile("cp.async.commit_group;" ::: "memory")
#define CP_WAIT0()  asm volatile("cp.async.wait_group 0;" ::: "memory")
#define CP_WAIT1()  asm volatile("cp.async.wait_group 1;" ::: "memory")
#define LDSM4(r, a) asm volatile( \
    "ldmatrix.sync.aligned.m8n8.x4.shared.b16 {%0,%1,%2,%3}, [%4];" \
    : "=r"((r)[0]), "=r"((r)[1]), "=r"((r)[2]), "=r"((r)[3]) : "r"(a))

__device__ __forceinline__ void mma16816(float* c, const uint32_t* a, const uint32_t* b) {
    asm volatile(
        "mma.sync.aligned.m16n8k16.row.col.f32.f16.f16.f32 "
        "{%0,%1,%2,%3}, {%4,%5,%6,%7}, {%8,%9}, {%0,%1,%2,%3};"
        : "+f"(c[0]), "+f"(c[1]), "+f"(c[2]), "+f"(c[3])
        : "r"(a[0]), "r"(a[1]), "r"(a[2]), "r"(a[3]), "r"(b[0]), "r"(b[1]));
}
__device__ __forceinline__ uint32_t sm_addr(const void* p) {
    return (uint32_t)__cvta_generic_to_shared(p);
}

// ---------------- mma.sync GEMM: 128x128 tile, A single fp16, B fp16 hi/lo ----------------
// C = A @ (Bh + Bl)^T [+bias][gelu]; 2 MMAs per fragment product.
// EPI: 1 f32+bias, 2 split fp16+bias, 3 single fp16+bias, 4 gelu single fp16
template <int EPI>
__global__ __launch_bounds__(256) void mmsync(
    const h16* __restrict__ Ah,
    const h16* __restrict__ Bh, const h16* __restrict__ Bl,
    const float* __restrict__ bias,
    float* __restrict__ Cf, h16* __restrict__ Ch, h16* __restrict__ Cl,
    int K, int lda, int ldb, int ldc)
{
    constexpr int SP  = 40;                // padded row stride (halfs) for BK=32
    constexpr int AST = 128 * SP;          // stage size (halfs)
    constexpr int MF  = 4;                 // warp tile 64x32
    constexpr int NF  = 4;

    extern __shared__ h16 sm[];
    h16* sA  = sm;                         // 2 * AST
    h16* sBH = sA + 2 * AST;
    h16* sBL = sBH + 2 * AST;

    const int tid = threadIdx.x;
    const int wid = tid >> 5;
    const int lane = tid & 31;
    const int gid = lane >> 2, tig = lane & 3;
    const int bm = blockIdx.y * 128;
    const int bn = blockIdx.x * 128;

    const int wm0 = (wid >> 2) * 64;       // 2 warp-rows x 4 warp-cols
    const int wn0 = (wid & 3) * 32;

    float acc[MF][NF][4];
#pragma unroll
    for (int i = 0; i < MF; i++)
#pragma unroll
        for (int j = 0; j < NF; j++)
#pragma unroll
            for (int q = 0; q < 4; q++) acc[i][j][q] = 0.f;

    const int nk = K >> 5;

    auto loadStage = [&](int st, int k0) {
#pragma unroll
        for (int i = 0; i < 2; i++) {
            int ch = tid + i * 256;        // 512 chunks: row = ch/4, c = ch%4
            int row = ch >> 2, c = ch & 3;
            size_t ga = (size_t)(bm + row) * lda + k0 + c * 8;
            size_t gb = (size_t)(bn + row) * ldb + k0 + c * 8;
            int so = st * AST + row * SP + c * 8;
            cpa16(sm_addr(&sA[so]),  Ah + ga);
            cpa16(sm_addr(&sBH[so]), Bh + gb);
            cpa16(sm_addr(&sBL[so]), Bl + gb);
        }
    };

    loadStage(0, 0);
    CP_COMMIT();

    const int ar = lane & 15;
    const int acb = (lane >> 4) << 3;
    const int br = (lane < 16) ? (lane & 7) : 8 + (lane & 7);
    const int bcsel = ((lane >> 3) & 1) << 3;

    for (int kt = 0; kt < nk; kt++) {
        if (kt + 1 < nk) {
            loadStage((kt + 1) & 1, (kt + 1) << 5);
            CP_COMMIT();
            CP_WAIT1();
        } else {
            CP_WAIT0();
        }
        __syncthreads();

        const int st = kt & 1;
        const h16* aP = sA + st * AST;
        const h16* bHp = sBH + st * AST;
        const h16* bLp = sBL + st * AST;

#pragma unroll
        for (int kk = 0; kk < 2; kk++) {
            const int koff = kk * 16;
            uint32_t af[MF][4];
#pragma unroll
            for (int mf = 0; mf < MF; mf++) {
                int r = wm0 + mf * 16 + ar;
                LDSM4(af[mf], sm_addr(&aP[r * SP + koff + acb]));
            }
            uint32_t bh[NF][2], bl[NF][2];
            const int bc = koff + bcsel;
#pragma unroll
            for (int nn = 0; nn < NF; nn += 2) {
                int r = wn0 + nn * 8 + br;
                uint32_t t[4];
                LDSM4(t, sm_addr(&bHp[r * SP + bc]));
                bh[nn][0] = t[0]; bh[nn][1] = t[1];
                bh[nn + 1][0] = t[2]; bh[nn + 1][1] = t[3];
                LDSM4(t, sm_addr(&bLp[r * SP + bc]));
                bl[nn][0] = t[0]; bl[nn][1] = t[1];
                bl[nn + 1][0] = t[2]; bl[nn + 1][1] = t[3];
            }
#pragma unroll
            for (int mf = 0; mf < MF; mf++)
#pragma unroll
                for (int nf = 0; nf < NF; nf++) {
                    mma16816(acc[mf][nf], af[mf], bh[nf]);
                    mma16816(acc[mf][nf], af[mf], bl[nf]);
                }
        }
        __syncthreads();
    }

    // ---------------- epilogue ----------------
#pragma unroll
    for (int mf = 0; mf < MF; mf++) {
        const int mA = bm + wm0 + mf * 16 + gid;
        const int mB = mA + 8;
#pragma unroll
        for (int nf = 0; nf < NF; nf++) {
            const int n = bn + wn0 + nf * 8 + 2 * tig;
            float c0 = acc[mf][nf][0], c1 = acc[mf][nf][1];
            float c2 = acc[mf][nf][2], c3 = acc[mf][nf][3];
            float b0 = bias[n], b1 = bias[n + 1];
            float v0 = c0 + b0, v1 = c1 + b1, v2 = c2 + b0, v3 = c3 + b1;
            if (EPI == 1) {
                *(float2*)(Cf + (size_t)mA * ldc + n) = make_float2(v0, v1);
                *(float2*)(Cf + (size_t)mB * ldc + n) = make_float2(v2, v3);
            } else if (EPI == 2) {
                h16 h0, l0, h1, l1, h2, l2, h3, l3;
                split_h(v0, h0, l0); split_h(v1, h1, l1);
                split_h(v2, h2, l2); split_h(v3, h3, l3);
                __half2 p;
                p.x = h0; p.y = h1; *(__half2*)(Ch + (size_t)mA * ldc + n) = p;
                p.x = l0; p.y = l1; *(__half2*)(Cl + (size_t)mA * ldc + n) = p;
                p.x = h2; p.y = h3; *(__half2*)(Ch + (size_t)mB * ldc + n) = p;
                p.x = l2; p.y = l3; *(__half2*)(Cl + (size_t)mB * ldc + n) = p;
            } else {
                if (EPI == 4) {
                    v0 = gelu_f(v0); v1 = gelu_f(v1);
                    v2 = gelu_f(v2); v3 = gelu_f(v3);
                }
                *(uint32_t*)(Ch + (size_t)mA * ldc + n) = pack2h(v0, v1);
                *(uint32_t*)(Ch + (size_t)mB * ldc + n) = pack2h(v2, v3);
            }
        }
    }
}

// ---------------- flash attention: S=QK^T/8, online softmax, O=PV ----------------
// grid (NH, SEQ/128), 256 threads (8 warps x 16 q-rows)
// Q single fp16, K hi/lo, V^T hi/lo, P single fp16; 2 MMAs per product.
__global__ __launch_bounds__(256) void flash_attn(
    const h16* __restrict__ qh_g,
    const h16* __restrict__ kh_g, const h16* __restrict__ kl_g,
    const h16* __restrict__ vth_g, const h16* __restrict__ vtl_g,
    h16* __restrict__ ch_g)
{
    constexpr int KSP = 72, VSP = 136;
    constexpr int KST = 128 * KSP;
    constexpr int VST = 64 * VSP;
    const int h = blockIdx.x;
    const int q0 = blockIdx.y * 128;
    const int tid = threadIdx.x, wid = tid >> 5, lane = tid & 31;
    const int gid = lane >> 2, tig = lane & 3;

    extern __shared__ h16 sm[];
    h16* sKH = sm;                         // 2 * KST
    h16* sKL = sKH + 2 * KST;
    h16* sVH = sKL + 2 * KST;              // 2 * VST
    h16* sVL = sVH + 2 * VST;

    // ---- prologue: Q tile (single) into stage-0 K buffer, extract frags ----
#pragma unroll
    for (int i = 0; i < 4; i++) {
        int ch = tid + i * 256;
        int row = ch >> 3, c = ch & 7;
        size_t g = (size_t)(q0 + row) * DM + h * 64 + c * 8;
        cpa16(sm_addr(&sKH[row * KSP + c * 8]), qh_g + g);
    }
    CP_COMMIT(); CP_WAIT0();
    __syncthreads();

    uint32_t qf[4][4];
    {
        const int ar = lane & 15, acb = (lane >> 4) << 3;
#pragma unroll
        for (int kf = 0; kf < 4; kf++) {
            int off = (wid * 16 + ar) * KSP + kf * 16 + acb;
            LDSM4(qf[kf], sm_addr(&sKH[off]));
        }
    }
    __syncthreads();

    float oacc[8][4];
#pragma unroll
    for (int i = 0; i < 8; i++)
#pragma unroll
        for (int q = 0; q < 4; q++) oacc[i][q] = 0.f;
    float m0 = -1e30f, m1 = -1e30f, l0 = 0.f, l1 = 0.f;

    auto loadKV = [&](int st, int s0) {
#pragma unroll
        for (int i = 0; i < 4; i++) {
            int ch = tid + i * 256;
            int row = ch >> 3, c = ch & 7;
            size_t g = (size_t)(s0 + row) * DM + h * 64 + c * 8;
            int so = st * KST + row * KSP + c * 8;
            cpa16(sm_addr(&sKH[so]), kh_g + g);
            cpa16(sm_addr(&sKL[so]), kl_g + g);
        }
#pragma unroll
        for (int i = 0; i < 4; i++) {
            int ch = tid + i * 256;
            int row = ch >> 4, c = ch & 15;
            size_t g = (size_t)(h * 64 + row) * SEQ + s0 + c * 8;
            int so = st * VST + row * VSP + c * 8;
            cpa16(sm_addr(&sVH[so]), vth_g + g);
            cpa16(sm_addr(&sVL[so]), vtl_g + g);
        }
    };

    loadKV(0, 0);
    CP_COMMIT();

    const int br = (lane < 16) ? (lane & 7) : 8 + (lane & 7);
    const int bcsel = ((lane >> 3) & 1) << 3;

    for (int kt = 0; kt < SEQ / 128; kt++) {
        if (kt + 1 < SEQ / 128) {
            loadKV((kt + 1) & 1, (kt + 1) * 128);
            CP_COMMIT();
            CP_WAIT1();
        } else {
            CP_WAIT0();
        }
        __syncthreads();

        const int st = kt & 1;
        const h16* kH = sKH + st * KST;
        const h16* kL = sKL + st * KST;
        const h16* vH = sVH + st * VST;
        const h16* vL = sVL + st * VST;

        float sacc[16][4];
#pragma unroll
        for (int i = 0; i < 16; i++)
#pragma unroll
            for (int q = 0; q < 4; q++) sacc[i][q] = 0.f;

#pragma unroll
        for (int kf = 0; kf < 4; kf++) {
            const int bc = kf * 16 + bcsel;
#pragma unroll
            for (int nn = 0; nn < 16; nn += 2) {
                uint32_t th[4], tl[4];
                LDSM4(th, sm_addr(&kH[(nn * 8 + br) * KSP + bc]));
                LDSM4(tl, sm_addr(&kL[(nn * 8 + br) * KSP + bc]));
                mma16816(sacc[nn], qf[kf], th);
                mma16816(sacc[nn], qf[kf], tl);
                mma16816(sacc[nn + 1], qf[kf], th + 2);
                mma16816(sacc[nn + 1], qf[kf], tl + 2);
            }
        }

        // scale + row max (rows gid / gid+8 of this warp's strip)
        float tm0 = -1e30f, tm1 = -1e30f;
#pragma unroll
        for (int nf = 0; nf < 16; nf++) {
            sacc[nf][0] *= 0.125f; sacc[nf][1] *= 0.125f;
            sacc[nf][2] *= 0.125f; sacc[nf][3] *= 0.125f;
            tm0 = fmaxf(tm0, fmaxf(sacc[nf][0], sacc[nf][1]));
            tm1 = fmaxf(tm1, fmaxf(sacc[nf][2], sacc[nf][3]));
        }
        tm0 = fmaxf(tm0, __shfl_xor_sync(0xffffffffu, tm0, 1));
        tm0 = fmaxf(tm0, __shfl_xor_sync(0xffffffffu, tm0, 2));
        tm1 = fmaxf(tm1, __shfl_xor_sync(0xffffffffu, tm1, 1));
        tm1 = fmaxf(tm1, __shfl_xor_sync(0xffffffffu, tm1, 2));

        const float mn0 = fmaxf(m0, tm0), mn1 = fmaxf(m1, tm1);
        const float a0 = __expf(m0 - mn0), a1 = __expf(m1 - mn1);

        float rs0 = 0.f, rs1 = 0.f;
#pragma unroll
        for (int nf = 0; nf < 16; nf++) {
            sacc[nf][0] = __expf(sacc[nf][0] - mn0);
            sacc[nf][1] = __expf(sacc[nf][1] - mn0);
            sacc[nf][2] = __expf(sacc[nf][2] - mn1);
            sacc[nf][3] = __expf(sacc[nf][3] - mn1);
            rs0 += sacc[nf][0] + sacc[nf][1];
            rs1 += sacc[nf][2] + sacc[nf][3];
        }
        rs0 += __shfl_xor_sync(0xffffffffu, rs0, 1);
        rs0 += __shfl_xor_sync(0xffffffffu, rs0, 2);
        rs1 += __shfl_xor_sync(0xffffffffu, rs1, 1);
        rs1 += __shfl_xor_sync(0xffffffffu, rs1, 2);

        m0 = mn0; m1 = mn1;
        l0 = l0 * a0 + rs0;
        l1 = l1 * a1 + rs1;

#pragma unroll
        for (int nf = 0; nf < 8; nf++) {
            oacc[nf][0] *= a0; oacc[nf][1] *= a0;
            oacc[nf][2] *= a1; oacc[nf][3] *= a1;
        }

        // O += P @ V   (P single fp16 from sacc regs, V^T hi/lo from smem)
#pragma unroll
        for (int j = 0; j < 8; j++) {
            uint32_t pa[4];
            pa[0] = pack2h(sacc[2 * j][0], sacc[2 * j][1]);
            pa[1] = pack2h(sacc[2 * j][2], sacc[2 * j][3]);
            pa[2] = pack2h(sacc[2 * j + 1][0], sacc[2 * j + 1][1]);
            pa[3] = pack2h(sacc[2 * j + 1][2], sacc[2 * j + 1][3]);
            const int bc = j * 16 + bcsel;
#pragma unroll
            for (int nn = 0; nn < 8; nn += 2) {
                uint32_t th[4], tl[4];
                LDSM4(th, sm_addr(&vH[(nn * 8 + br) * VSP + bc]));
                LDSM4(tl, sm_addr(&vL[(nn * 8 + br) * VSP + bc]));
                mma16816(oacc[nn], pa, th);
                mma16816(oacc[nn], pa, tl);
                mma16816(oacc[nn + 1], pa, th + 2);
                mma16816(oacc[nn + 1], pa, tl + 2);
            }
        }
        __syncthreads();
    }

    // ---- epilogue: O/l, store ctx single fp16 ----
    const float il0 = 1.f / l0, il1 = 1.f / l1;
    const int mA = q0 + wid * 16 + gid;
    const int mB = mA + 8;
#pragma unroll
    for (int nf = 0; nf < 8; nf++) {
        const int col = h * 64 + nf * 8 + 2 * tig;
        *(uint32_t*)(ch_g + (size_t)mA * DM + col) =
            pack2h(oacc[nf][0] * il0, oacc[nf][1] * il0);
        *(uint32_t*)(ch_g + (size_t)mB * DM + col) =
            pack2h(oacc[nf][2] * il1, oacc[nf][3] * il1);
    }
}

// ---------------- transpose + split weights: W[R,C] fp32 -> WT[C,R] fp16 hi/lo ----------------
__global__ void trans_split_k(const float* __restrict__ in, h16* __restrict__ oh,
                              h16* __restrict__ ol, int R, int C)
{
    __shared__ float t[32][33];
    const size_t zo = (size_t)blockIdx.z * R * C;
    in += zo; oh += zo; ol += zo;
    const int r0 = blockIdx.y * 32, c0 = blockIdx.x * 32;
    const int tx = threadIdx.x, ty = threadIdx.y;
#pragma unroll
    for (int i = 0; i < 32; i += 8)
        t[ty + i][tx] = in[(size_t)(r0 + ty + i) * C + c0 + tx];
    __syncthreads();
#pragma unroll
    for (int i = 0; i < 32; i += 8) {
        float v = t[tx][ty + i];
        h16 h, l; split_h(v, h, l);
        size_t o = (size_t)(c0 + ty + i) * R + r0 + tx;
        oh[o] = h; ol[o] = l;
    }
}

// ---------------- transpose two fp16 matrices [R,C] -> [C,R] ----------------
__global__ void trans2_h_k(const h16* __restrict__ a, h16* __restrict__ at,
                           const h16* __restrict__ b, h16* __restrict__ bt,
                           int R, int C)
{
    __shared__ h16 ta[32][33], tb[32][33];
    const int r0 = blockIdx.y * 32, c0 = blockIdx.x * 32;
    const int tx = threadIdx.x, ty = threadIdx.y;
#pragma unroll
    for (int i = 0; i < 32; i += 8) {
        size_t g = (size_t)(r0 + ty + i) * C + c0 + tx;
        ta[ty + i][tx] = a[g];
        tb[ty + i][tx] = b[g];
    }
    __syncthreads();
#pragma unroll
    for (int i = 0; i < 32; i += 8) {
        size_t o = (size_t)(c0 + ty + i) * R + r0 + tx;
        at[o] = ta[tx][ty + i];
        bt[o] = tb[tx][ty + i];
    }
}

// ---------------- elementwise fp32 -> fp16 ----------------
__global__ void cvt_h_k(const float* __restrict__ x, h16* __restrict__ h, int n)
{
    int i = blockIdx.x * 256 + threadIdx.x;
    if (i < n) h[i] = __float2half_rn(x[i]);
}

// ---------------- residual + LayerNorm, writes x fp32 and single fp16 ----------------
__global__ __launch_bounds__(256) void add_ln_k(
    float* __restrict__ x, const float* __restrict__ y,
    const float* __restrict__ g, const float* __restrict__ b,
    h16* __restrict__ xh)
{
    __shared__ float r[DM];
    __shared__ float red[256];
    const int tid = threadIdx.x;
    const size_t off = (size_t)blockIdx.x * DM;

    float lsum = 0.f;
    for (int j = tid; j < DM; j += 256) {
        float v = x[off + j] + y[off + j];
        r[j] = v;
        lsum += v;
    }
    red[tid] = lsum; __syncthreads();
    for (int st = 128; st > 0; st >>= 1) {
        if (tid < st) red[tid] += red[tid + st];
        __syncthreads();
    }
    const float mu = red[0] * (1.0f / DM);
    __syncthreads();

    float lv = 0.f;
    for (int j = tid; j < DM; j += 256) {
        float d = r[j] - mu;
        lv += d * d;
    }
    red[tid] = lv; __syncthreads();
    for (int st = 128; st > 0; st >>= 1) {
        if (tid < st) red[tid] += red[tid + st];
        __syncthreads();
    }
    const float rstd = rsqrtf(red[0] * (1.0f / DM) + 1e-5f);

    for (int j = tid; j < DM; j += 256) {
        float v = (r[j] - mu) * rstd * g[j] + b[j];
        x[off + j] = v;
        xh[off + j] = __float2half_rn(v);
    }
}

// ---------------- host launch ----------------
static const int SMEMMM = 3 * 2 * 128 * 40 * 2;                      // 61440
static const int SMEMFA = (2 * 128 * 72 * 2 + 2 * 64 * 136 * 2) * 2; // 143360

extern "C" void kernel_launch(void* const* d_in, const int* in_sizes, int n_in,
                              void* d_out, int out_size)
{
    const float* x_in = (const float*)d_in[0];
    const float* wq = (const float*)d_in[1];
    const float* bq = (const float*)d_in[2];
    const float* wk = (const float*)d_in[3];
    const float* bk = (const float*)d_in[4];
    const float* wv = (const float*)d_in[5];
    const float* bv = (const float*)d_in[6];
    const float* wo = (const float*)d_in[7];
    const float* bo = (const float*)d_in[8];
    const float* w1 = (const float*)d_in[9];
    const float* b1 = (const float*)d_in[10];
    const float* w2 = (const float*)d_in[11];
    const float* b2 = (const float*)d_in[12];
    const float* ln1g = (const float*)d_in[13];
    const float* ln1b = (const float*)d_in[14];
    const float* ln2g = (const float*)d_in[15];
    const float* ln2b = (const float*)d_in[16];

    float* x = (float*)d_out;

    h16 *wqTh, *wqTl, *wkTh, *wkTl, *wvTh, *wvTl, *woTh, *woTl;
    h16 *w1Th, *w1Tl, *w2Th, *w2Tl;
    h16 *xh, *qh, *kh, *kl, *vh, *vl, *vth, *vtl, *ch, *hh;
    float *tmp;
    cudaGetSymbolAddress((void**)&wqTh, g_wqT_h); cudaGetSymbolAddress((void**)&wqTl, g_wqT_l);
    cudaGetSymbolAddress((void**)&wkTh, g_wkT_h); cudaGetSymbolAddress((void**)&wkTl, g_wkT_l);
    cudaGetSymbolAddress((void**)&wvTh, g_wvT_h); cudaGetSymbolAddress((void**)&wvTl, g_wvT_l);
    cudaGetSymbolAddress((void**)&woTh, g_woT_h); cudaGetSymbolAddress((void**)&woTl, g_woT_l);
    cudaGetSymbolAddress((void**)&w1Th, g_w1T_h); cudaGetSymbolAddress((void**)&w1Tl, g_w1T_l);
    cudaGetSymbolAddress((void**)&w2Th, g_w2T_h); cudaGetSymbolAddress((void**)&w2Tl, g_w2T_l);
    cudaGetSymbolAddress((void**)&xh, g_xh);
    cudaGetSymbolAddress((void**)&qh, g_qh);
    cudaGetSymbolAddress((void**)&kh, g_kh); cudaGetSymbolAddress((void**)&kl, g_kl);
    cudaGetSymbolAddress((void**)&vh, g_vh); cudaGetSymbolAddress((void**)&vl, g_vl);
    cudaGetSymbolAddress((void**)&vth, g_vth); cudaGetSymbolAddress((void**)&vtl, g_vtl);
    cudaGetSymbolAddress((void**)&ch, g_ch);
    cudaGetSymbolAddress((void**)&hh, g_hh);
    cudaGetSymbolAddress((void**)&tmp, g_tmp);

    cudaFuncSetAttribute(mmsync<1>, cudaFuncAttributeMaxDynamicSharedMemorySize, SMEMMM);
    cudaFuncSetAttribute(mmsync<2>, cudaFuncAttributeMaxDynamicSharedMemorySize, SMEMMM);
    cudaFuncSetAttribute(mmsync<3>, cudaFuncAttributeMaxDynamicSharedMemorySize, SMEMMM);
    cudaFuncSetAttribute(mmsync<4>, cudaFuncAttributeMaxDynamicSharedMemorySize, SMEMMM);
    cudaFuncSetAttribute(flash_attn, cudaFuncAttributeMaxDynamicSharedMemorySize, SMEMFA);

    const dim3 tb(32, 8);
    trans_split_k<<<dim3(DM / 32, DM / 32, NL), tb>>>(wq, wqTh, wqTl, DM, DM);
    trans_split_k<<<dim3(DM / 32, DM / 32, NL), tb>>>(wk, wkTh, wkTl, DM, DM);
    trans_split_k<<<dim3(DM / 32, DM / 32, NL), tb>>>(wv, wvTh, wvTl, DM, DM);
    trans_split_k<<<dim3(DM / 32, DM / 32, NL), tb>>>(wo, woTh, woTl, DM, DM);
    trans_split_k<<<dim3(DFF / 32, DM / 32, NL), tb>>>(w1, w1Th, w1Tl, DM, DFF);
    trans_split_k<<<dim3(DM / 32, DFF / 32, NL), tb>>>(w2, w2Th, w2Tl, DFF, DM);

    cudaMemcpyAsync(x, x_in, (size_t)SEQ * DM * sizeof(float), cudaMemcpyDeviceToDevice);
    cvt_h_k<<<(SEQ * DM) / 256, 256>>>(x_in, xh, SEQ * DM);

    const dim3 gP(DM / 128, SEQ / 128);       // (8,16)
    const dim3 gFA(NH, SEQ / 128);            // (16,16)
    const dim3 gF1(DFF / 128, SEQ / 128);     // (32,16)

    for (int l = 0; l < NL; l++) {
        const size_t lW = (size_t)l * DM * DM;
        const size_t lF = (size_t)l * DM * DFF;

        // q single fp16; k, v split fp16
        mmsync<3><<<gP, 256, SMEMMM>>>(xh, wqTh + lW, wqTl + lW, bq + l * DM,
            nullptr, qh, nullptr, DM, DM, DM, DM);
        mmsync<2><<<gP, 256, SMEMMM>>>(xh, wkTh + lW, wkTl + lW, bk + l * DM,
            nullptr, kh, kl, DM, DM, DM, DM);
        mmsync<2><<<gP, 256, SMEMMM>>>(xh, wvTh + lW, wvTl + lW, bv + l * DM,
            nullptr, vh, vl, DM, DM, DM, DM);
        trans2_h_k<<<dim3(DM / 32, SEQ / 32), tb>>>(vh, vth, vl, vtl, SEQ, DM);

        // fused attention: scores + softmax + AV
        flash_attn<<<gFA, 256, SMEMFA>>>(qh, kh, kl, vth, vtl, ch);

        mmsync<1><<<gP, 256, SMEMMM>>>(ch, woTh + lW, woTl + lW, bo + l * DM,
            tmp, nullptr, nullptr, DM, DM, DM, DM);

        add_ln_k<<<SEQ, 256>>>(x, tmp, ln1g + l * DM, ln1b + l * DM, xh);

        mmsync<4><<<gF1, 256, SMEMMM>>>(xh, w1Th + lF, w1Tl + lF, b1 + l * DFF,
            nullptr, hh, nullptr, DM, DM, DM, DFF);

        mmsync<1><<<gP, 256, SMEMMM>>>(hh, w2Th + lF, w2Tl + lF, b2 + l * DM,
            tmp, nullptr, nullptr, DFF, DFF, DFF, DM);

        add_ln_k<<<SEQ, 256>>>(x, tmp, ln2g + l * DM, ln2b + l * DM, xh);
    }
}

// round 13
// speedup vs baseline: 3.1454x; 1.5322x over previous
#include <cuda_runtime.h>
#include <cuda_fp16.h>
#include <math.h>
#include <stdint.h>

#define SEQ 2048
#define DM  1024
#define NH  16
#define DK  64
#define DFF 4096
#define NL  4

typedef __half h16;

// ---------------- device scratch (no cudaMalloc allowed) ----------------
__device__ h16 g_wqT[NL * DM * DM];
__device__ h16 g_wkT[NL * DM * DM];
__device__ h16 g_wvT[NL * DM * DM];
__device__ h16 g_woT[NL * DM * DM];
__device__ h16 g_w1T[NL * DM * DFF];
__device__ h16 g_w2T[NL * DM * DFF];
__device__ h16 g_xh[SEQ * DM];
__device__ h16 g_qh[SEQ * DM];
__device__ h16 g_kh[SEQ * DM];
__device__ h16 g_vh[SEQ * DM];
__device__ h16 g_vth[DM * SEQ];          // V^T
__device__ h16 g_ch[SEQ * DM];
__device__ h16 g_hh[SEQ * DFF];
__device__ float g_tmp[SEQ * DM];

// ---------------- small helpers ----------------
__device__ __forceinline__ float tanh_fast(float y) {
    // tanh(y) = 1 - 2/(e^{2y}+1), MUFU-based, fp32-accurate ~1e-6
    return 1.0f - 2.0f / (__expf(2.0f * y) + 1.0f);
}
__device__ __forceinline__ float gelu_f(float v) {
    return 0.5f * v * (1.0f + tanh_fast(0.7978845608028654f *
                                        (v + 0.044715f * v * v * v)));
}
__device__ __forceinline__ uint32_t pack2h(float x, float y) {
    __half2 p = __floats2half2_rn(x, y);
    return *(uint32_t*)&p;
}
__device__ __forceinline__ void cpa16(uint32_t dst, const void* src) {
    asm volatile("cp.async.cg.shared.global [%0], [%1], 16;" :: "r"(dst), "l"(src));
}
#define CP_COMMIT() asm volatile("cp.async.commit_group;" ::: "memory")
#define CP_WAIT0()  asm volatile("cp.async.wait_group 0;" ::: "memory")
#define CP_WAIT1()  asm volatile("cp.async.wait_group 1;" ::: "memory")
#define LDSM4(r, a) asm volatile( \
    "ldmatrix.sync.aligned.m8n8.x4.shared.b16 {%0,%1,%2,%3}, [%4];" \
    : "=r"((r)[0]), "=r"((r)[1]), "=r"((r)[2]), "=r"((r)[3]) : "r"(a))

__device__ __forceinline__ void mma16816(float* c, const uint32_t* a, const uint32_t* b) {
    asm volatile(
        "mma.sync.aligned.m16n8k16.row.col.f32.f16.f16.f32 "
        "{%0,%1,%2,%3}, {%4,%5,%6,%7}, {%8,%9}, {%0,%1,%2,%3};"
        : "+f"(c[0]), "+f"(c[1]), "+f"(c[2]), "+f"(c[3])
        : "r"(a[0]), "r"(a[1]), "r"(a[2]), "r"(a[3]), "r"(b[0]), "r"(b[1]));
}
__device__ __forceinline__ uint32_t sm_addr(const void* p) {
    return (uint32_t)__cvta_generic_to_shared(p);
}

// ---------------- mma.sync GEMM: 128x128 tile, pure fp16 operands, fp32 accum ----------------
// C = A @ B^T [+bias][gelu]
// EPI: 1 f32+bias, 3 fp16+bias, 4 gelu fp16+bias
template <int EPI>
__global__ __launch_bounds__(256) void mmsync(
    const h16* __restrict__ Ah, const h16* __restrict__ Bh,
    const float* __restrict__ bias,
    float* __restrict__ Cf, h16* __restrict__ Ch,
    int K, int lda, int ldb, int ldc)
{
    constexpr int SP  = 40;                // padded row stride (halfs) for BK=32
    constexpr int AST = 128 * SP;          // stage size (halfs)
    constexpr int MF  = 4;                 // warp tile 64x32
    constexpr int NF  = 4;

    extern __shared__ h16 sm[];
    h16* sA = sm;                          // 2 * AST
    h16* sB = sA + 2 * AST;                // 2 * AST

    const int tid = threadIdx.x;
    const int wid = tid >> 5;
    const int lane = tid & 31;
    const int gid = lane >> 2, tig = lane & 3;
    const int bm = blockIdx.y * 128;
    const int bn = blockIdx.x * 128;

    const int wm0 = (wid >> 2) * 64;       // 2 warp-rows x 4 warp-cols
    const int wn0 = (wid & 3) * 32;

    float acc[MF][NF][4];
#pragma unroll
    for (int i = 0; i < MF; i++)
#pragma unroll
        for (int j = 0; j < NF; j++)
#pragma unroll
            for (int q = 0; q < 4; q++) acc[i][j][q] = 0.f;

    const int nk = K >> 5;

    auto loadStage = [&](int st, int k0) {
#pragma unroll
        for (int i = 0; i < 2; i++) {
            int ch = tid + i * 256;        // 512 chunks: row = ch/4, c = ch%4
            int row = ch >> 2, c = ch & 3;
            size_t ga = (size_t)(bm + row) * lda + k0 + c * 8;
            size_t gb = (size_t)(bn + row) * ldb + k0 + c * 8;
            int so = st * AST + row * SP + c * 8;
            cpa16(sm_addr(&sA[so]), Ah + ga);
            cpa16(sm_addr(&sB[so]), Bh + gb);
        }
    };

    loadStage(0, 0);
    CP_COMMIT();

    const int ar = lane & 15;
    const int acb = (lane >> 4) << 3;
    const int br = (lane < 16) ? (lane & 7) : 8 + (lane & 7);
    const int bcsel = ((lane >> 3) & 1) << 3;

    for (int kt = 0; kt < nk; kt++) {
        if (kt + 1 < nk) {
            loadStage((kt + 1) & 1, (kt + 1) << 5);
            CP_COMMIT();
            CP_WAIT1();
        } else {
            CP_WAIT0();
        }
        __syncthreads();

        const int st = kt & 1;
        const h16* aP = sA + st * AST;
        const h16* bP = sB + st * AST;

#pragma unroll
        for (int kk = 0; kk < 2; kk++) {
            const int koff = kk * 16;
            uint32_t af[MF][4];
#pragma unroll
            for (int mf = 0; mf < MF; mf++) {
                int r = wm0 + mf * 16 + ar;
                LDSM4(af[mf], sm_addr(&aP[r * SP + koff + acb]));
            }
            uint32_t bf[NF][2];
            const int bc = koff + bcsel;
#pragma unroll
            for (int nn = 0; nn < NF; nn += 2) {
                int r = wn0 + nn * 8 + br;
                uint32_t t[4];
                LDSM4(t, sm_addr(&bP[r * SP + bc]));
                bf[nn][0] = t[0]; bf[nn][1] = t[1];
                bf[nn + 1][0] = t[2]; bf[nn + 1][1] = t[3];
            }
#pragma unroll
            for (int mf = 0; mf < MF; mf++)
#pragma unroll
                for (int nf = 0; nf < NF; nf++)
                    mma16816(acc[mf][nf], af[mf], bf[nf]);
        }
        __syncthreads();
    }

    // ---------------- epilogue ----------------
#pragma unroll
    for (int mf = 0; mf < MF; mf++) {
        const int mA = bm + wm0 + mf * 16 + gid;
        const int mB = mA + 8;
#pragma unroll
        for (int nf = 0; nf < NF; nf++) {
            const int n = bn + wn0 + nf * 8 + 2 * tig;
            float b0 = bias[n], b1 = bias[n + 1];
            float v0 = acc[mf][nf][0] + b0, v1 = acc[mf][nf][1] + b1;
            float v2 = acc[mf][nf][2] + b0, v3 = acc[mf][nf][3] + b1;
            if (EPI == 1) {
                *(float2*)(Cf + (size_t)mA * ldc + n) = make_float2(v0, v1);
                *(float2*)(Cf + (size_t)mB * ldc + n) = make_float2(v2, v3);
            } else {
                if (EPI == 4) {
                    v0 = gelu_f(v0); v1 = gelu_f(v1);
                    v2 = gelu_f(v2); v3 = gelu_f(v3);
                }
                *(uint32_t*)(Ch + (size_t)mA * ldc + n) = pack2h(v0, v1);
                *(uint32_t*)(Ch + (size_t)mB * ldc + n) = pack2h(v2, v3);
            }
        }
    }
}

// ---------------- flash attention: S=QK^T/8, online softmax, O=PV ----------------
// grid (NH, SEQ/128), 256 threads (8 warps x 16 q-rows), pure fp16 operands
__global__ __launch_bounds__(256) void flash_attn(
    const h16* __restrict__ qh_g, const h16* __restrict__ kh_g,
    const h16* __restrict__ vth_g, h16* __restrict__ ch_g)
{
    constexpr int KSP = 72, VSP = 136;
    constexpr int KST = 128 * KSP;
    constexpr int VST = 64 * VSP;
    const int h = blockIdx.x;
    const int q0 = blockIdx.y * 128;
    const int tid = threadIdx.x, wid = tid >> 5, lane = tid & 31;
    const int gid = lane >> 2, tig = lane & 3;

    extern __shared__ h16 sm[];
    h16* sK = sm;                          // 2 * KST
    h16* sV = sK + 2 * KST;                // 2 * VST

    // ---- prologue: Q tile into stage-0 K buffer, extract frags ----
#pragma unroll
    for (int i = 0; i < 4; i++) {
        int ch = tid + i * 256;
        int row = ch >> 3, c = ch & 7;
        size_t g = (size_t)(q0 + row) * DM + h * 64 + c * 8;
        cpa16(sm_addr(&sK[row * KSP + c * 8]), qh_g + g);
    }
    CP_COMMIT(); CP_WAIT0();
    __syncthreads();

    uint32_t qf[4][4];
    {
        const int ar = lane & 15, acb = (lane >> 4) << 3;
#pragma unroll
        for (int kf = 0; kf < 4; kf++) {
            int off = (wid * 16 + ar) * KSP + kf * 16 + acb;
            LDSM4(qf[kf], sm_addr(&sK[off]));
        }
    }
    __syncthreads();

    float oacc[8][4];
#pragma unroll
    for (int i = 0; i < 8; i++)
#pragma unroll
        for (int q = 0; q < 4; q++) oacc[i][q] = 0.f;
    float m0 = -1e30f, m1 = -1e30f, l0 = 0.f, l1 = 0.f;

    auto loadKV = [&](int st, int s0) {
        // K tile: 128 rows x 64 halfs = 1024 chunks of 8
#pragma unroll
        for (int i = 0; i < 4; i++) {
            int ch = tid + i * 256;
            int row = ch >> 3, c = ch & 7;
            size_t g = (size_t)(s0 + row) * DM + h * 64 + c * 8;
            cpa16(sm_addr(&sK[st * KST + row * KSP + c * 8]), kh_g + g);
        }
        // V tile: 64 rows x 128 halfs = 1024 chunks of 8
#pragma unroll
        for (int i = 0; i < 4; i++) {
            int ch = tid + i * 256;
            int row = ch >> 4, c = ch & 15;
            size_t g = (size_t)(h * 64 + row) * SEQ + s0 + c * 8;
            cpa16(sm_addr(&sV[st * VST + row * VSP + c * 8]), vth_g + g);
        }
    };

    loadKV(0, 0);
    CP_COMMIT();

    const int br = (lane < 16) ? (lane & 7) : 8 + (lane & 7);
    const int bcsel = ((lane >> 3) & 1) << 3;

    for (int kt = 0; kt < SEQ / 128; kt++) {
        if (kt + 1 < SEQ / 128) {
            loadKV((kt + 1) & 1, (kt + 1) * 128);
            CP_COMMIT();
            CP_WAIT1();
        } else {
            CP_WAIT0();
        }
        __syncthreads();

        const int st = kt & 1;
        const h16* kP = sK + st * KST;
        const h16* vP = sV + st * VST;

        float sacc[16][4];
#pragma unroll
        for (int i = 0; i < 16; i++)
#pragma unroll
            for (int q = 0; q < 4; q++) sacc[i][q] = 0.f;

#pragma unroll
        for (int kf = 0; kf < 4; kf++) {
            const int bc = kf * 16 + bcsel;
#pragma unroll
            for (int nn = 0; nn < 16; nn += 2) {
                uint32_t t[4];
                LDSM4(t, sm_addr(&kP[(nn * 8 + br) * KSP + bc]));
                mma16816(sacc[nn], qf[kf], t);
                mma16816(sacc[nn + 1], qf[kf], t + 2);
            }
        }

        // scale + row max (rows gid / gid+8 of this warp's strip)
        float tm0 = -1e30f, tm1 = -1e30f;
#pragma unroll
        for (int nf = 0; nf < 16; nf++) {
            sacc[nf][0] *= 0.125f; sacc[nf][1] *= 0.125f;
            sacc[nf][2] *= 0.125f; sacc[nf][3] *= 0.125f;
            tm0 = fmaxf(tm0, fmaxf(sacc[nf][0], sacc[nf][1]));
            tm1 = fmaxf(tm1, fmaxf(sacc[nf][2], sacc[nf][3]));
        }
        tm0 = fmaxf(tm0, __shfl_xor_sync(0xffffffffu, tm0, 1));
        tm0 = fmaxf(tm0, __shfl_xor_sync(0xffffffffu, tm0, 2));
        tm1 = fmaxf(tm1, __shfl_xor_sync(0xffffffffu, tm1, 1));
        tm1 = fmaxf(tm1, __shfl_xor_sync(0xffffffffu, tm1, 2));

        const float mn0 = fmaxf(m0, tm0), mn1 = fmaxf(m1, tm1);
        const float a0 = __expf(m0 - mn0), a1 = __expf(m1 - mn1);

        float rs0 = 0.f, rs1 = 0.f;
#pragma unroll
        for (int nf = 0; nf < 16; nf++) {
            sacc[nf][0] = __expf(sacc[nf][0] - mn0);
            sacc[nf][1] = __expf(sacc[nf][1] - mn0);
            sacc[nf][2] = __expf(sacc[nf][2] - mn1);
            sacc[nf][3] = __expf(sacc[nf][3] - mn1);
            rs0 += sacc[nf][0] + sacc[nf][1];
            rs1 += sacc[nf][2] + sacc[nf][3];
        }
        rs0 += __shfl_xor_sync(0xffffffffu, rs0, 1);
        rs0 += __shfl_xor_sync(0xffffffffu, rs0, 2);
        rs1 += __shfl_xor_sync(0xffffffffu, rs1, 1);
        rs1 += __shfl_xor_sync(0xffffffffu, rs1, 2);

        m0 = mn0; m1 = mn1;
        l0 = l0 * a0 + rs0;
        l1 = l1 * a1 + rs1;

#pragma unroll
        for (int nf = 0; nf < 8; nf++) {
            oacc[nf][0] *= a0; oacc[nf][1] *= a0;
            oacc[nf][2] *= a1; oacc[nf][3] *= a1;
        }

        // O += P @ V   (P single fp16 from sacc regs, V^T from smem)
#pragma unroll
        for (int j = 0; j < 8; j++) {
            uint32_t pa[4];
            pa[0] = pack2h(sacc[2 * j][0], sacc[2 * j][1]);
            pa[1] = pack2h(sacc[2 * j][2], sacc[2 * j][3]);
            pa[2] = pack2h(sacc[2 * j + 1][0], sacc[2 * j + 1][1]);
            pa[3] = pack2h(sacc[2 * j + 1][2], sacc[2 * j + 1][3]);
            const int bc = j * 16 + bcsel;
#pragma unroll
            for (int nn = 0; nn < 8; nn += 2) {
                uint32_t t[4];
                LDSM4(t, sm_addr(&vP[(nn * 8 + br) * VSP + bc]));
                mma16816(oacc[nn], pa, t);
                mma16816(oacc[nn + 1], pa, t + 2);
            }
        }
        __syncthreads();
    }

    // ---- epilogue: O/l, store ctx fp16 ----
    const float il0 = 1.f / l0, il1 = 1.f / l1;
    const int mA = q0 + wid * 16 + gid;
    const int mB = mA + 8;
#pragma unroll
    for (int nf = 0; nf < 8; nf++) {
        const int col = h * 64 + nf * 8 + 2 * tig;
        *(uint32_t*)(ch_g + (size_t)mA * DM + col) =
            pack2h(oacc[nf][0] * il0, oacc[nf][1] * il0);
        *(uint32_t*)(ch_g + (size_t)mB * DM + col) =
            pack2h(oacc[nf][2] * il1, oacc[nf][3] * il1);
    }
}

// ---------------- transpose + convert weights: W[R,C] fp32 -> WT[C,R] fp16 ----------------
__global__ void trans_cvt_k(const float* __restrict__ in, h16* __restrict__ oh,
                            int R, int C)
{
    __shared__ float t[32][33];
    const size_t zo = (size_t)blockIdx.z * R * C;
    in += zo; oh += zo;
    const int r0 = blockIdx.y * 32, c0 = blockIdx.x * 32;
    const int tx = threadIdx.x, ty = threadIdx.y;
#pragma unroll
    for (int i = 0; i < 32; i += 8)
        t[ty + i][tx] = in[(size_t)(r0 + ty + i) * C + c0 + tx];
    __syncthreads();
#pragma unroll
    for (int i = 0; i < 32; i += 8)
        oh[(size_t)(c0 + ty + i) * R + r0 + tx] = __float2half_rn(t[tx][ty + i]);
}

// ---------------- transpose fp16 matrix [R,C] -> [C,R] ----------------
__global__ void trans_h_k(const h16* __restrict__ a, h16* __restrict__ at,
                          int R, int C)
{
    __shared__ h16 ta[32][33];
    const int r0 = blockIdx.y * 32, c0 = blockIdx.x * 32;
    const int tx = threadIdx.x, ty = threadIdx.y;
#pragma unroll
    for (int i = 0; i < 32; i += 8)
        ta[ty + i][tx] = a[(size_t)(r0 + ty + i) * C + c0 + tx];
    __syncthreads();
#pragma unroll
    for (int i = 0; i < 32; i += 8)
        at[(size_t)(c0 + ty + i) * R + r0 + tx] = ta[tx][ty + i];
}

// ---------------- elementwise fp32 -> fp16 ----------------
__global__ void cvt_h_k(const float* __restrict__ x, h16* __restrict__ h, int n)
{
    int i = blockIdx.x * 256 + threadIdx.x;
    if (i < n) h[i] = __float2half_rn(x[i]);
}

// ---------------- residual + LayerNorm, writes x fp32 and fp16 ----------------
__global__ __launch_bounds__(256) void add_ln_k(
    float* __restrict__ x, const float* __restrict__ y,
    const float* __restrict__ g, const float* __restrict__ b,
    h16* __restrict__ xh)
{
    __shared__ float r[DM];
    __shared__ float red[256];
    const int tid = threadIdx.x;
    const size_t off = (size_t)blockIdx.x * DM;

    float lsum = 0.f;
    for (int j = tid; j < DM; j += 256) {
        float v = x[off + j] + y[off + j];
        r[j] = v;
        lsum += v;
    }
    red[tid] = lsum; __syncthreads();
    for (int st = 128; st > 0; st >>= 1) {
        if (tid < st) red[tid] += red[tid + st];
        __syncthreads();
    }
    const float mu = red[0] * (1.0f / DM);
    __syncthreads();

    float lv = 0.f;
    for (int j = tid; j < DM; j += 256) {
        float d = r[j] - mu;
        lv += d * d;
    }
    red[tid] = lv; __syncthreads();
    for (int st = 128; st > 0; st >>= 1) {
        if (tid < st) red[tid] += red[tid + st];
        __syncthreads();
    }
    const float rstd = rsqrtf(red[0] * (1.0f / DM) + 1e-5f);

    for (int j = tid; j < DM; j += 256) {
        float v = (r[j] - mu) * rstd * g[j] + b[j];
        x[off + j] = v;
        xh[off + j] = __float2half_rn(v);
    }
}

// ---------------- host launch ----------------
static const int SMEMMM = 2 * 2 * 128 * 40 * 2;                  // 40960
static const int SMEMFA = (2 * 128 * 72 + 2 * 64 * 136) * 2;     // 71680

extern "C" void kernel_launch(void* const* d_in, const int* in_sizes, int n_in,
                              void* d_out, int out_size)
{
    const float* x_in = (const float*)d_in[0];
    const float* wq = (const float*)d_in[1];
    const float* bq = (const float*)d_in[2];
    const float* wk = (const float*)d_in[3];
    const float* bk = (const float*)d_in[4];
    const float* wv = (const float*)d_in[5];
    const float* bv = (const float*)d_in[6];
    const float* wo = (const float*)d_in[7];
    const float* bo = (const float*)d_in[8];
    const float* w1 = (const float*)d_in[9];
    const float* b1 = (const float*)d_in[10];
    const float* w2 = (const float*)d_in[11];
    const float* b2 = (const float*)d_in[12];
    const float* ln1g = (const float*)d_in[13];
    const float* ln1b = (const float*)d_in[14];
    const float* ln2g = (const float*)d_in[15];
    const float* ln2b = (const float*)d_in[16];

    float* x = (float*)d_out;

    h16 *wqT, *wkT, *wvT, *woT, *w1T, *w2T;
    h16 *xh, *qh, *kh, *vh, *vth, *ch, *hh;
    float *tmp;
    cudaGetSymbolAddress((void**)&wqT, g_wqT);
    cudaGetSymbolAddress((void**)&wkT, g_wkT);
    cudaGetSymbolAddress((void**)&wvT, g_wvT);
    cudaGetSymbolAddress((void**)&woT, g_woT);
    cudaGetSymbolAddress((void**)&w1T, g_w1T);
    cudaGetSymbolAddress((void**)&w2T, g_w2T);
    cudaGetSymbolAddress((void**)&xh, g_xh);
    cudaGetSymbolAddress((void**)&qh, g_qh);
    cudaGetSymbolAddress((void**)&kh, g_kh);
    cudaGetSymbolAddress((void**)&vh, g_vh);
    cudaGetSymbolAddress((void**)&vth, g_vth);
    cudaGetSymbolAddress((void**)&ch, g_ch);
    cudaGetSymbolAddress((void**)&hh, g_hh);
    cudaGetSymbolAddress((void**)&tmp, g_tmp);

    cudaFuncSetAttribute(mmsync<1>, cudaFuncAttributeMaxDynamicSharedMemorySize, SMEMMM);
    cudaFuncSetAttribute(mmsync<3>, cudaFuncAttributeMaxDynamicSharedMemorySize, SMEMMM);
    cudaFuncSetAttribute(mmsync<4>, cudaFuncAttributeMaxDynamicSharedMemorySize, SMEMMM);
    cudaFuncSetAttribute(flash_attn, cudaFuncAttributeMaxDynamicSharedMemorySize, SMEMFA);

    const dim3 tb(32, 8);
    trans_cvt_k<<<dim3(DM / 32, DM / 32, NL), tb>>>(wq, wqT, DM, DM);
    trans_cvt_k<<<dim3(DM / 32, DM / 32, NL), tb>>>(wk, wkT, DM, DM);
    trans_cvt_k<<<dim3(DM / 32, DM / 32, NL), tb>>>(wv, wvT, DM, DM);
    trans_cvt_k<<<dim3(DM / 32, DM / 32, NL), tb>>>(wo, woT, DM, DM);
    trans_cvt_k<<<dim3(DFF / 32, DM / 32, NL), tb>>>(w1, w1T, DM, DFF);
    trans_cvt_k<<<dim3(DM / 32, DFF / 32, NL), tb>>>(w2, w2T, DFF, DM);

    cudaMemcpyAsync(x, x_in, (size_t)SEQ * DM * sizeof(float), cudaMemcpyDeviceToDevice);
    cvt_h_k<<<(SEQ * DM) / 256, 256>>>(x_in, xh, SEQ * DM);

    const dim3 gP(DM / 128, SEQ / 128);       // (8,16)
    const dim3 gFA(NH, SEQ / 128);            // (16,16)
    const dim3 gF1(DFF / 128, SEQ / 128);     // (32,16)

    for (int l = 0; l < NL; l++) {
        const size_t lW = (size_t)l * DM * DM;
        const size_t lF = (size_t)l * DM * DFF;

        mmsync<3><<<gP, 256, SMEMMM>>>(xh, wqT + lW, bq + l * DM,
            nullptr, qh, DM, DM, DM, DM);
        mmsync<3><<<gP, 256, SMEMMM>>>(xh, wkT + lW, bk + l * DM,
            nullptr, kh, DM, DM, DM, DM);
        mmsync<3><<<gP, 256, SMEMMM>>>(xh, wvT + lW, bv + l * DM,
            nullptr, vh, DM, DM, DM, DM);
        trans_h_k<<<dim3(DM / 32, SEQ / 32), tb>>>(vh, vth, SEQ, DM);

        // fused attention: scores + softmax + AV
        flash_attn<<<gFA, 256, SMEMFA>>>(qh, kh, vth, ch);

        mmsync<1><<<gP, 256, SMEMMM>>>(ch, woT + lW, bo + l * DM,
            tmp, nullptr, DM, DM, DM, DM);

        add_ln_k<<<SEQ, 256>>>(x, tmp, ln1g + l * DM, ln1b + l * DM, xh);

        mmsync<4><<<gF1, 256, SMEMMM>>>(xh, w1T + lF, b1 + l * DFF,
            nullptr, hh, DM, DM, DM, DFF);

        mmsync<1><<<gP, 256, SMEMMM>>>(hh, w2T + lF, b2 + l * DM,
            tmp, nullptr, DFF, DFF, DFF, DM);

        add_ln_k<<<SEQ, 256>>>(x, tmp, ln2g + l * DM, ln2b + l * DM, xh);
    }
}

// round 14
// speedup vs baseline: 3.4165x; 1.0862x over previous
#include <cuda_runtime.h>
#include <cuda_fp16.h>
#include <math.h>
#include <stdint.h>

#define SEQ 2048
#define DM  1024
#define NH  16
#define DK  64
#define DFF 4096
#define NL  4
#define LDQKV (3 * DM)

typedef __half h16;

// ---------------- device scratch (no cudaMalloc allowed) ----------------
__device__ h16 g_wqkvT[NL * 3 * DM * DM];     // [3*DM rows, DM cols] per layer
__device__ float g_bqkv[NL * 3 * DM];
__device__ h16 g_woT[NL * DM * DM];
__device__ h16 g_w1T[NL * DM * DFF];
__device__ h16 g_w2T[NL * DM * DFF];
__device__ h16 g_xh[SEQ * DM];
__device__ h16 g_qkv[SEQ * 3 * DM];           // fused q|k|v
__device__ h16 g_vth[DM * SEQ];               // V^T
__device__ h16 g_ch[SEQ * DM];
__device__ h16 g_hh[SEQ * DFF];
__device__ float g_tmp[SEQ * DM];

// ---------------- small helpers ----------------
__device__ __forceinline__ float tanh_fast(float y) {
    return 1.0f - 2.0f / (__expf(2.0f * y) + 1.0f);
}
__device__ __forceinline__ float gelu_f(float v) {
    return 0.5f * v * (1.0f + tanh_fast(0.7978845608028654f *
                                        (v + 0.044715f * v * v * v)));
}
__device__ __forceinline__ uint32_t pack2h(float x, float y) {
    __half2 p = __floats2half2_rn(x, y);
    return *(uint32_t*)&p;
}
__device__ __forceinline__ void cpa16(uint32_t dst, const void* src) {
    asm volatile("cp.async.cg.shared.global [%0], [%1], 16;" :: "r"(dst), "l"(src));
}
#define CP_COMMIT() asm volatile("cp.async.commit_group;" ::: "memory")
#define CP_WAIT0()  asm volatile("cp.async.wait_group 0;" ::: "memory")
#define CP_WAIT1()  asm volatile("cp.async.wait_group 1;" ::: "memory")
#define LDSM4(r, a) asm volatile( \
    "ldmatrix.sync.aligned.m8n8.x4.shared.b16 {%0,%1,%2,%3}, [%4];" \
    : "=r"((r)[0]), "=r"((r)[1]), "=r"((r)[2]), "=r"((r)[3]) : "r"(a))

__device__ __forceinline__ void mma16816(float* c, const uint32_t* a, const uint32_t* b) {
    asm volatile(
        "mma.sync.aligned.m16n8k16.row.col.f32.f16.f16.f32 "
        "{%0,%1,%2,%3}, {%4,%5,%6,%7}, {%8,%9}, {%0,%1,%2,%3};"
        : "+f"(c[0]), "+f"(c[1]), "+f"(c[2]), "+f"(c[3])
        : "r"(a[0]), "r"(a[1]), "r"(a[2]), "r"(a[3]), "r"(b[0]), "r"(b[1]));
}
__device__ __forceinline__ uint32_t sm_addr(const void* p) {
    return (uint32_t)__cvta_generic_to_shared(p);
}

// ---------------- mma.sync GEMM: 128x128 tile, pure fp16, 2 CTA/SM ----------------
// C = A @ B^T [+bias][gelu]
// EPI: 1 f32+bias, 3 fp16+bias, 4 gelu fp16+bias
template <int EPI>
__global__ __launch_bounds__(256, 2) void mmsync(
    const h16* __restrict__ Ah, const h16* __restrict__ Bh,
    const float* __restrict__ bias,
    float* __restrict__ Cf, h16* __restrict__ Ch,
    int K, int lda, int ldb, int ldc)
{
    constexpr int SP  = 40;
    constexpr int AST = 128 * SP;
    constexpr int MF  = 4;
    constexpr int NF  = 4;

    extern __shared__ h16 sm[];
    h16* sA = sm;                          // 2 * AST
    h16* sB = sA + 2 * AST;                // 2 * AST

    const int tid = threadIdx.x;
    const int wid = tid >> 5;
    const int lane = tid & 31;
    const int gid = lane >> 2, tig = lane & 3;
    const int bm = blockIdx.y * 128;
    const int bn = blockIdx.x * 128;

    const int wm0 = (wid >> 2) * 64;
    const int wn0 = (wid & 3) * 32;

    float acc[MF][NF][4];
#pragma unroll
    for (int i = 0; i < MF; i++)
#pragma unroll
        for (int j = 0; j < NF; j++)
#pragma unroll
            for (int q = 0; q < 4; q++) acc[i][j][q] = 0.f;

    const int nk = K >> 5;

    auto loadStage = [&](int st, int k0) {
#pragma unroll
        for (int i = 0; i < 2; i++) {
            int ch = tid + i * 256;
            int row = ch >> 2, c = ch & 3;
            size_t ga = (size_t)(bm + row) * lda + k0 + c * 8;
            size_t gb = (size_t)(bn + row) * ldb + k0 + c * 8;
            int so = st * AST + row * SP + c * 8;
            cpa16(sm_addr(&sA[so]), Ah + ga);
            cpa16(sm_addr(&sB[so]), Bh + gb);
        }
    };

    loadStage(0, 0);
    CP_COMMIT();

    const int ar = lane & 15;
    const int acb = (lane >> 4) << 3;
    const int br = (lane < 16) ? (lane & 7) : 8 + (lane & 7);
    const int bcsel = ((lane >> 3) & 1) << 3;

    for (int kt = 0; kt < nk; kt++) {
        if (kt + 1 < nk) {
            loadStage((kt + 1) & 1, (kt + 1) << 5);
            CP_COMMIT();
            CP_WAIT1();
        } else {
            CP_WAIT0();
        }
        __syncthreads();

        const int st = kt & 1;
        const h16* aP = sA + st * AST;
        const h16* bP = sB + st * AST;

#pragma unroll
        for (int kk = 0; kk < 2; kk++) {
            const int koff = kk * 16;
            uint32_t af[MF][4];
#pragma unroll
            for (int mf = 0; mf < MF; mf++) {
                int r = wm0 + mf * 16 + ar;
                LDSM4(af[mf], sm_addr(&aP[r * SP + koff + acb]));
            }
            uint32_t bf[NF][2];
            const int bc = koff + bcsel;
#pragma unroll
            for (int nn = 0; nn < NF; nn += 2) {
                int r = wn0 + nn * 8 + br;
                uint32_t t[4];
                LDSM4(t, sm_addr(&bP[r * SP + bc]));
                bf[nn][0] = t[0]; bf[nn][1] = t[1];
                bf[nn + 1][0] = t[2]; bf[nn + 1][1] = t[3];
            }
#pragma unroll
            for (int mf = 0; mf < MF; mf++)
#pragma unroll
                for (int nf = 0; nf < NF; nf++)
                    mma16816(acc[mf][nf], af[mf], bf[nf]);
        }
        __syncthreads();
    }

    // ---------------- epilogue ----------------
#pragma unroll
    for (int mf = 0; mf < MF; mf++) {
        const int mA = bm + wm0 + mf * 16 + gid;
        const int mB = mA + 8;
#pragma unroll
        for (int nf = 0; nf < NF; nf++) {
            const int n = bn + wn0 + nf * 8 + 2 * tig;
            float b0 = bias[n], b1 = bias[n + 1];
            float v0 = acc[mf][nf][0] + b0, v1 = acc[mf][nf][1] + b1;
            float v2 = acc[mf][nf][2] + b0, v3 = acc[mf][nf][3] + b1;
            if (EPI == 1) {
                *(float2*)(Cf + (size_t)mA * ldc + n) = make_float2(v0, v1);
                *(float2*)(Cf + (size_t)mB * ldc + n) = make_float2(v2, v3);
            } else {
                if (EPI == 4) {
                    v0 = gelu_f(v0); v1 = gelu_f(v1);
                    v2 = gelu_f(v2); v3 = gelu_f(v3);
                }
                *(uint32_t*)(Ch + (size_t)mA * ldc + n) = pack2h(v0, v1);
                *(uint32_t*)(Ch + (size_t)mB * ldc + n) = pack2h(v2, v3);
            }
        }
    }
}

// ---------------- flash attention: S=QK^T/8, online softmax, O=PV ----------------
// grid (NH, SEQ/128), 256 threads. Q/K read from fused qkv (stride LDQKV).
__global__ __launch_bounds__(256) void flash_attn(
    const h16* __restrict__ qkv_g,      // q at +0, k at +DM, stride LDQKV
    const h16* __restrict__ vth_g,      // V^T [DM, SEQ]
    h16* __restrict__ ch_g)
{
    constexpr int KSP = 72, VSP = 136;
    constexpr int KST = 128 * KSP;
    constexpr int VST = 64 * VSP;
    const int h = blockIdx.x;
    const int q0 = blockIdx.y * 128;
    const int tid = threadIdx.x, wid = tid >> 5, lane = tid & 31;
    const int gid = lane >> 2, tig = lane & 3;

    const h16* qh_g = qkv_g;
    const h16* kh_g = qkv_g + DM;

    extern __shared__ h16 sm[];
    h16* sK = sm;                          // 2 * KST
    h16* sV = sK + 2 * KST;                // 2 * VST

    // ---- prologue: Q tile into stage-0 K buffer, extract frags ----
#pragma unroll
    for (int i = 0; i < 4; i++) {
        int ch = tid + i * 256;
        int row = ch >> 3, c = ch & 7;
        size_t g = (size_t)(q0 + row) * LDQKV + h * 64 + c * 8;
        cpa16(sm_addr(&sK[row * KSP + c * 8]), qh_g + g);
    }
    CP_COMMIT(); CP_WAIT0();
    __syncthreads();

    uint32_t qf[4][4];
    {
        const int ar = lane & 15, acb = (lane >> 4) << 3;
#pragma unroll
        for (int kf = 0; kf < 4; kf++) {
            int off = (wid * 16 + ar) * KSP + kf * 16 + acb;
            LDSM4(qf[kf], sm_addr(&sK[off]));
        }
    }
    __syncthreads();

    float oacc[8][4];
#pragma unroll
    for (int i = 0; i < 8; i++)
#pragma unroll
        for (int q = 0; q < 4; q++) oacc[i][q] = 0.f;
    float m0 = -1e30f, m1 = -1e30f, l0 = 0.f, l1 = 0.f;

    auto loadKV = [&](int st, int s0) {
        // K tile: 128 rows x 64 halfs = 1024 chunks of 8
#pragma unroll
        for (int i = 0; i < 4; i++) {
            int ch = tid + i * 256;
            int row = ch >> 3, c = ch & 7;
            size_t g = (size_t)(s0 + row) * LDQKV + h * 64 + c * 8;
            cpa16(sm_addr(&sK[st * KST + row * KSP + c * 8]), kh_g + g);
        }
        // V tile: 64 rows x 128 halfs = 1024 chunks of 8
#pragma unroll
        for (int i = 0; i < 4; i++) {
            int ch = tid + i * 256;
            int row = ch >> 4, c = ch & 15;
            size_t g = (size_t)(h * 64 + row) * SEQ + s0 + c * 8;
            cpa16(sm_addr(&sV[st * VST + row * VSP + c * 8]), vth_g + g);
        }
    };

    loadKV(0, 0);
    CP_COMMIT();

    const int br = (lane < 16) ? (lane & 7) : 8 + (lane & 7);
    const int bcsel = ((lane >> 3) & 1) << 3;

    for (int kt = 0; kt < SEQ / 128; kt++) {
        if (kt + 1 < SEQ / 128) {
            loadKV((kt + 1) & 1, (kt + 1) * 128);
            CP_COMMIT();
            CP_WAIT1();
        } else {
            CP_WAIT0();
        }
        __syncthreads();

        const int st = kt & 1;
        const h16* kP = sK + st * KST;
        const h16* vP = sV + st * VST;

        float sacc[16][4];
#pragma unroll
        for (int i = 0; i < 16; i++)
#pragma unroll
            for (int q = 0; q < 4; q++) sacc[i][q] = 0.f;

#pragma unroll
        for (int kf = 0; kf < 4; kf++) {
            const int bc = kf * 16 + bcsel;
#pragma unroll
            for (int nn = 0; nn < 16; nn += 2) {
                uint32_t t[4];
                LDSM4(t, sm_addr(&kP[(nn * 8 + br) * KSP + bc]));
                mma16816(sacc[nn], qf[kf], t);
                mma16816(sacc[nn + 1], qf[kf], t + 2);
            }
        }

        float tm0 = -1e30f, tm1 = -1e30f;
#pragma unroll
        for (int nf = 0; nf < 16; nf++) {
            sacc[nf][0] *= 0.125f; sacc[nf][1] *= 0.125f;
            sacc[nf][2] *= 0.125f; sacc[nf][3] *= 0.125f;
            tm0 = fmaxf(tm0, fmaxf(sacc[nf][0], sacc[nf][1]));
            tm1 = fmaxf(tm1, fmaxf(sacc[nf][2], sacc[nf][3]));
        }
        tm0 = fmaxf(tm0, __shfl_xor_sync(0xffffffffu, tm0, 1));
        tm0 = fmaxf(tm0, __shfl_xor_sync(0xffffffffu, tm0, 2));
        tm1 = fmaxf(tm1, __shfl_xor_sync(0xffffffffu, tm1, 1));
        tm1 = fmaxf(tm1, __shfl_xor_sync(0xffffffffu, tm1, 2));

        const float mn0 = fmaxf(m0, tm0), mn1 = fmaxf(m1, tm1);
        const float a0 = __expf(m0 - mn0), a1 = __expf(m1 - mn1);

        float rs0 = 0.f, rs1 = 0.f;
#pragma unroll
        for (int nf = 0; nf < 16; nf++) {
            sacc[nf][0] = __expf(sacc[nf][0] - mn0);
            sacc[nf][1] = __expf(sacc[nf][1] - mn0);
            sacc[nf][2] = __expf(sacc[nf][2] - mn1);
            sacc[nf][3] = __expf(sacc[nf][3] - mn1);
            rs0 += sacc[nf][0] + sacc[nf][1];
            rs1 += sacc[nf][2] + sacc[nf][3];
        }
        rs0 += __shfl_xor_sync(0xffffffffu, rs0, 1);
        rs0 += __shfl_xor_sync(0xffffffffu, rs0, 2);
        rs1 += __shfl_xor_sync(0xffffffffu, rs1, 1);
        rs1 += __shfl_xor_sync(0xffffffffu, rs1, 2);

        m0 = mn0; m1 = mn1;
        l0 = l0 * a0 + rs0;
        l1 = l1 * a1 + rs1;

#pragma unroll
        for (int nf = 0; nf < 8; nf++) {
            oacc[nf][0] *= a0; oacc[nf][1] *= a0;
            oacc[nf][2] *= a1; oacc[nf][3] *= a1;
        }

#pragma unroll
        for (int j = 0; j < 8; j++) {
            uint32_t pa[4];
            pa[0] = pack2h(sacc[2 * j][0], sacc[2 * j][1]);
            pa[1] = pack2h(sacc[2 * j][2], sacc[2 * j][3]);
            pa[2] = pack2h(sacc[2 * j + 1][0], sacc[2 * j + 1][1]);
            pa[3] = pack2h(sacc[2 * j + 1][2], sacc[2 * j + 1][3]);
            const int bc = j * 16 + bcsel;
#pragma unroll
            for (int nn = 0; nn < 8; nn += 2) {
                uint32_t t[4];
                LDSM4(t, sm_addr(&vP[(nn * 8 + br) * VSP + bc]));
                mma16816(oacc[nn], pa, t);
                mma16816(oacc[nn + 1], pa, t + 2);
            }
        }
        __syncthreads();
    }

    // ---- epilogue: O/l, store ctx fp16 ----
    const float il0 = 1.f / l0, il1 = 1.f / l1;
    const int mA = q0 + wid * 16 + gid;
    const int mB = mA + 8;
#pragma unroll
    for (int nf = 0; nf < 8; nf++) {
        const int col = h * 64 + nf * 8 + 2 * tig;
        *(uint32_t*)(ch_g + (size_t)mA * DM + col) =
            pack2h(oacc[nf][0] * il0, oacc[nf][1] * il0);
        *(uint32_t*)(ch_g + (size_t)mB * DM + col) =
            pack2h(oacc[nf][2] * il1, oacc[nf][3] * il1);
    }
}

// ---------------- transpose + convert weights: W[R,C] fp32 -> WT[C,R] fp16 ----------------
// per-z strides passed explicitly (for packing QKV into one buffer)
__global__ void trans_cvt_k(const float* __restrict__ in, h16* __restrict__ oh,
                            int R, int C, long long izs, long long ozs)
{
    __shared__ float t[32][33];
    in += (size_t)blockIdx.z * izs;
    oh += (size_t)blockIdx.z * ozs;
    const int r0 = blockIdx.y * 32, c0 = blockIdx.x * 32;
    const int tx = threadIdx.x, ty = threadIdx.y;
#pragma unroll
    for (int i = 0; i < 32; i += 8)
        t[ty + i][tx] = in[(size_t)(r0 + ty + i) * C + c0 + tx];
    __syncthreads();
#pragma unroll
    for (int i = 0; i < 32; i += 8)
        oh[(size_t)(c0 + ty + i) * R + r0 + tx] = __float2half_rn(t[tx][ty + i]);
}

// ---------------- bias concat: [bq|bk|bv] per layer ----------------
__global__ void concat_bias_k(const float* __restrict__ bq, const float* __restrict__ bk,
                              const float* __restrict__ bv, float* __restrict__ out)
{
    int l = blockIdx.x, w = blockIdx.y, i = threadIdx.x;
    const float* s = (w == 0) ? bq : ((w == 1) ? bk : bv);
    out[(size_t)(l * 3 + w) * DM + i] = s[(size_t)l * DM + i];
}

// ---------------- strided fp16 transpose: a[R,C] (lda) -> at[C,R] (ldat) ----------------
__global__ void trans_h_k(const h16* __restrict__ a, h16* __restrict__ at,
                          int lda, int ldat)
{
    __shared__ h16 ta[32][33];
    const int r0 = blockIdx.y * 32, c0 = blockIdx.x * 32;
    const int tx = threadIdx.x, ty = threadIdx.y;
#pragma unroll
    for (int i = 0; i < 32; i += 8)
        ta[ty + i][tx] = a[(size_t)(r0 + ty + i) * lda + c0 + tx];
    __syncthreads();
#pragma unroll
    for (int i = 0; i < 32; i += 8)
        at[(size_t)(c0 + ty + i) * ldat + r0 + tx] = ta[tx][ty + i];
}

// ---------------- elementwise fp32 -> fp16 ----------------
__global__ void cvt_h_k(const float* __restrict__ x, h16* __restrict__ h, int n)
{
    int i = blockIdx.x * 256 + threadIdx.x;
    if (i < n) h[i] = __float2half_rn(x[i]);
}

// ---------------- residual + LayerNorm, writes x fp32 and fp16 ----------------
__global__ __launch_bounds__(256) void add_ln_k(
    float* __restrict__ x, const float* __restrict__ y,
    const float* __restrict__ g, const float* __restrict__ b,
    h16* __restrict__ xh)
{
    __shared__ float r[DM];
    __shared__ float red[256];
    const int tid = threadIdx.x;
    const size_t off = (size_t)blockIdx.x * DM;

    float lsum = 0.f;
    for (int j = tid; j < DM; j += 256) {
        float v = x[off + j] + y[off + j];
        r[j] = v;
        lsum += v;
    }
    red[tid] = lsum; __syncthreads();
    for (int st = 128; st > 0; st >>= 1) {
        if (tid < st) red[tid] += red[tid + st];
        __syncthreads();
    }
    const float mu = red[0] * (1.0f / DM);
    __syncthreads();

    float lv = 0.f;
    for (int j = tid; j < DM; j += 256) {
        float d = r[j] - mu;
        lv += d * d;
    }
    red[tid] = lv; __syncthreads();
    for (int st = 128; st > 0; st >>= 1) {
        if (tid < st) red[tid] += red[tid + st];
        __syncthreads();
    }
    const float rstd = rsqrtf(red[0] * (1.0f / DM) + 1e-5f);

    for (int j = tid; j < DM; j += 256) {
        float v = (r[j] - mu) * rstd * g[j] + b[j];
        x[off + j] = v;
        xh[off + j] = __float2half_rn(v);
    }
}

// ---------------- host launch ----------------
static const int SMEMMM = 2 * 2 * 128 * 40 * 2;                  // 40960
static const int SMEMFA = (2 * 128 * 72 + 2 * 64 * 136) * 2;     // 71680

extern "C" void kernel_launch(void* const* d_in, const int* in_sizes, int n_in,
                              void* d_out, int out_size)
{
    const float* x_in = (const float*)d_in[0];
    const float* wq = (const float*)d_in[1];
    const float* bq = (const float*)d_in[2];
    const float* wk = (const float*)d_in[3];
    const float* bk = (const float*)d_in[4];
    const float* wv = (const float*)d_in[5];
    const float* bv = (const float*)d_in[6];
    const float* wo = (const float*)d_in[7];
    const float* bo = (const float*)d_in[8];
    const float* w1 = (const float*)d_in[9];
    const float* b1 = (const float*)d_in[10];
    const float* w2 = (const float*)d_in[11];
    const float* b2 = (const float*)d_in[12];
    const float* ln1g = (const float*)d_in[13];
    const float* ln1b = (const float*)d_in[14];
    const float* ln2g = (const float*)d_in[15];
    const float* ln2b = (const float*)d_in[16];

    float* x = (float*)d_out;

    h16 *wqkvT, *woT, *w1T, *w2T;
    h16 *xh, *qkv, *vth, *ch, *hh;
    float *tmp, *bqkv;
    cudaGetSymbolAddress((void**)&wqkvT, g_wqkvT);
    cudaGetSymbolAddress((void**)&bqkv, g_bqkv);
    cudaGetSymbolAddress((void**)&woT, g_woT);
    cudaGetSymbolAddress((void**)&w1T, g_w1T);
    cudaGetSymbolAddress((void**)&w2T, g_w2T);
    cudaGetSymbolAddress((void**)&xh, g_xh);
    cudaGetSymbolAddress((void**)&qkv, g_qkv);
    cudaGetSymbolAddress((void**)&vth, g_vth);
    cudaGetSymbolAddress((void**)&ch, g_ch);
    cudaGetSymbolAddress((void**)&hh, g_hh);
    cudaGetSymbolAddress((void**)&tmp, g_tmp);

    cudaFuncSetAttribute(mmsync<1>, cudaFuncAttributeMaxDynamicSharedMemorySize, SMEMMM);
    cudaFuncSetAttribute(mmsync<3>, cudaFuncAttributeMaxDynamicSharedMemorySize, SMEMMM);
    cudaFuncSetAttribute(mmsync<4>, cudaFuncAttributeMaxDynamicSharedMemorySize, SMEMMM);
    cudaFuncSetAttribute(flash_attn, cudaFuncAttributeMaxDynamicSharedMemorySize, SMEMFA);

    const dim3 tb(32, 8);
    const long long WZ = (long long)DM * DM;
    const long long QZ = 3LL * DM * DM;
    // QKV weights packed: rows [0,DM)=wq, [DM,2DM)=wk, [2DM,3DM)=wv
    trans_cvt_k<<<dim3(DM / 32, DM / 32, NL), tb>>>(wq, wqkvT, DM, DM, WZ, QZ);
    trans_cvt_k<<<dim3(DM / 32, DM / 32, NL), tb>>>(wk, wqkvT + (size_t)DM * DM, DM, DM, WZ, QZ);
    trans_cvt_k<<<dim3(DM / 32, DM / 32, NL), tb>>>(wv, wqkvT + 2 * (size_t)DM * DM, DM, DM, WZ, QZ);
    trans_cvt_k<<<dim3(DM / 32, DM / 32, NL), tb>>>(wo, woT, DM, DM, WZ, WZ);
    trans_cvt_k<<<dim3(DFF / 32, DM / 32, NL), tb>>>(w1, w1T, DM, DFF,
        (long long)DM * DFF, (long long)DM * DFF);
    trans_cvt_k<<<dim3(DM / 32, DFF / 32, NL), tb>>>(w2, w2T, DFF, DM,
        (long long)DM * DFF, (long long)DM * DFF);
    concat_bias_k<<<dim3(NL, 3), DM>>>(bq, bk, bv, bqkv);

    cudaMemcpyAsync(x, x_in, (size_t)SEQ * DM * sizeof(float), cudaMemcpyDeviceToDevice);
    cvt_h_k<<<(SEQ * DM) / 256, 256>>>(x_in, xh, SEQ * DM);

    const dim3 gQKV(3 * DM / 128, SEQ / 128);  // (24,16)
    const dim3 gP(DM / 128, SEQ / 128);        // (8,16)
    const dim3 gFA(NH, SEQ / 128);             // (16,16)
    const dim3 gF1(DFF / 128, SEQ / 128);      // (32,16)

    for (int l = 0; l < NL; l++) {
        const size_t lW = (size_t)l * DM * DM;
        const size_t lQ = (size_t)l * 3 * DM * DM;
        const size_t lF = (size_t)l * DM * DFF;

        // fused q|k|v projection
        mmsync<3><<<gQKV, 256, SMEMMM>>>(xh, wqkvT + lQ, bqkv + (size_t)l * 3 * DM,
            nullptr, qkv, DM, DM, DM, LDQKV);
        // V^T from qkv's v slice (stride LDQKV)
        trans_h_k<<<dim3(DM / 32, SEQ / 32), tb>>>(qkv + 2 * DM, vth, LDQKV, SEQ);

        // fused attention: scores + softmax + AV
        flash_attn<<<gFA, 256, SMEMFA>>>(qkv, vth, ch);

        mmsync<1><<<gP, 256, SMEMMM>>>(ch, woT + lW, bo + l * DM,
            tmp, nullptr, DM, DM, DM, DM);

        add_ln_k<<<SEQ, 256>>>(x, tmp, ln1g + l * DM, ln1b + l * DM, xh);

        mmsync<4><<<gF1, 256, SMEMMM>>>(xh, w1T + lF, b1 + l * DFF,
            nullptr, hh, DM, DM, DM, DFF);

        mmsync<1><<<gP, 256, SMEMMM>>>(hh, w2T + lF, b2 + l * DM,
            tmp, nullptr, DFF, DFF, DFF, DM);

        add_ln_k<<<SEQ, 256>>>(x, tmp, ln2g + l * DM, ln2b + l * DM, xh);
    }
}